// round 2
// baseline (speedup 1.0000x reference)
#include <cuda_runtime.h>

#define NN   10000
#define EE   160000
#define BB   8
#define HH   64
#define PART 320            // 5 slots * 64 features per (node,batch) row
#define NB   (NN*BB)        // 80000

// ---------------- device scratch ----------------
__device__ float g_deg_out[NN];
__device__ float g_deg_in[NN];
__device__ int   g_cnt[2][NN];
__device__ int   g_off[2][NN+1];
__device__ int   g_cur[2][NN];
__device__ int   g_nbr[2][EE];
__device__ float g_wgt[2][EE];

__device__ float g_vx[NB*PART];   // x-part slots: 0=x 1=A_f x 2=A_r x 3=cheb_f 4=cheb_r
__device__ float g_vh[NB*PART];   // h-part slots
__device__ float g_vr[NB*PART];   // (R*h)-part slots
__device__ float g_z [NB*HH];     // Z gate
__device__ float g_WZR[640*128];  // concat weights for Z|R gemm
__device__ float g_WH [640*64];   // concat weights for H gemm

// ---------------- packed f32x2 helpers ----------------
__device__ __forceinline__ void ffma2(unsigned long long &acc,
                                      unsigned long long a,
                                      unsigned long long b) {
    asm("fma.rn.f32x2 %0, %1, %2, %0;" : "+l"(acc) : "l"(a), "l"(b));
}
__device__ __forceinline__ unsigned long long dup2(float a) {
    unsigned long long r;
    asm("mov.b64 %0, {%1, %1};" : "=l"(r) : "r"(__float_as_uint(a)));
    return r;
}
__device__ __forceinline__ void unpack2(unsigned long long v, float &lo, float &hi) {
    unsigned l, h;
    asm("mov.b64 {%0, %1}, %2;" : "=r"(l), "=r"(h) : "l"(v));
    lo = __uint_as_float(l); hi = __uint_as_float(h);
}
__device__ __forceinline__ float sigm(float x) { return 1.f / (1.f + __expf(-x)); }

__device__ __forceinline__ float* partbuf(int id) {
    return id == 0 ? g_vx : (id == 1 ? g_vh : g_vr);
}

// ---------------- setup ----------------
__global__ void k_zero() {
    int i = blockIdx.x * 256 + threadIdx.x;
    if (i < NN) {
        g_deg_out[i] = 0.f; g_deg_in[i] = 0.f;
        g_cnt[0][i] = 0;    g_cnt[1][i] = 0;
    }
}

__global__ void k_degcnt(const float* __restrict__ ew, const int* __restrict__ ei) {
    int e = blockIdx.x * 256 + threadIdx.x;
    if (e >= EE) return;
    int s = ei[e], d = ei[EE + e];
    float w = ew[e];
    atomicAdd(&g_deg_out[s], w);
    atomicAdd(&g_deg_in[d],  w);
    atomicAdd(&g_cnt[0][d], 1);   // fwd CSR keyed by dst
    atomicAdd(&g_cnt[1][s], 1);   // rev CSR keyed by src
}

__global__ void k_scan() {   // grid=2, block=1024
    int d = blockIdx.x;
    __shared__ int sums[1024];
    int t = threadIdx.x;
    const int CH = 10;
    int base = t * CH;
    int s = 0;
    for (int i = 0; i < CH; i++) { int idx = base + i; if (idx < NN) s += g_cnt[d][idx]; }
    sums[t] = s; __syncthreads();
    for (int off = 1; off < 1024; off <<= 1) {
        int v = (t >= off) ? sums[t - off] : 0;
        __syncthreads();
        sums[t] += v;
        __syncthreads();
    }
    int run = (t == 0) ? 0 : sums[t - 1];
    for (int i = 0; i < CH; i++) {
        int idx = base + i;
        if (idx < NN) { g_off[d][idx] = run; g_cur[d][idx] = run; run += g_cnt[d][idx]; }
    }
    if (t == 1023) g_off[d][NN] = run;
}

__global__ void k_fill(const float* __restrict__ ew, const int* __restrict__ ei) {
    int e = blockIdx.x * 256 + threadIdx.x;
    if (e >= EE) return;
    int s = ei[e], d = ei[EE + e];
    float w = ew[e];
    float wo = g_deg_out[s]; float nout = w / (wo > 0.f ? wo : 1.f);
    float wi = g_deg_in[d];  float nin  = w / (wi > 0.f ? wi : 1.f);
    int p = atomicAdd(&g_cur[0][d], 1); g_nbr[0][p] = s; g_wgt[0][p] = nout;
    int q = atomicAdd(&g_cur[1][s], 1); g_nbr[1][q] = d; g_wgt[1][q] = nin;
}

__global__ void k_init_x(const float* __restrict__ go) {
    int t = blockIdx.x * 256 + threadIdx.x;
    if (t >= NB * HH) return;
    int f = t & 63; int rest = t >> 6;
    int n = rest % NN; int b = rest / NN;
    g_vx[(n * BB + b) * PART + f] = go[t];
}

__global__ void k_load_h(const float* __restrict__ hs, int l) {
    int t = blockIdx.x * 256 + threadIdx.x;
    if (t >= NB * HH) return;
    int f = t & 63; int rest = t >> 6;
    int n = rest % NN; int b = rest / NN;
    g_vh[(n * BB + b) * PART + f] = hs[(size_t)l * NB * HH + t];
}

// W layout [L,2,K,128,64]. Slots: 0:(dir0+dir1,k0) 1:(0,k1) 2:(1,k1) 3:(0,k2) 4:(1,k2)
__device__ __forceinline__ float wslot(const float* W, int l, int s, int wrow, int o) {
    if (s == 0) {
        return W[((((l*2+0)*3+0)*128 + wrow)*64) + o] +
               W[((((l*2+1)*3+0)*128 + wrow)*64) + o];
    }
    int dir = (s == 1 || s == 3) ? 0 : 1;
    int k   = (s <= 2) ? 1 : 2;
    return W[((((l*2+dir)*3+k)*128 + wrow)*64) + o];
}

__global__ void k_build_wzr(const float* __restrict__ Wz, const float* __restrict__ Wr, int l) {
    int idx = blockIdx.x * 256 + threadIdx.x;
    if (idx >= 640 * 128) return;
    int j = idx >> 7, c = idx & 127;
    int p = j / 320, s = (j % 320) / 64, f = j & 63;
    int wrow = p * 64 + f;
    const float* W = (c < 64) ? Wz : Wr;
    g_WZR[j * 128 + c] = wslot(W, l, s, wrow, c & 63);
}

__global__ void k_build_wh(const float* __restrict__ Wh, int l) {
    int idx = blockIdx.x * 256 + threadIdx.x;
    if (idx >= 640 * 64) return;
    int j = idx >> 6, o = idx & 63;
    int p = j / 320, s = (j % 320) / 64, f = j & 63;
    g_WH[j * 64 + o] = wslot(Wh, l, s, p * 64 + f, o);
}

// ---------------- propagation ----------------
// block = node, warp = batch, lane = 2 features
__global__ void __launch_bounds__(256) k_prop(int bufA, int bufB, int s_in, int s_out,
                                              int cheb, int s_prev, int dir) {
    float* buf = partbuf(blockIdx.y == 0 ? bufA : bufB);
    const int*   off = g_off[dir];
    const int*   nbr = g_nbr[dir];
    const float* wgt = g_wgt[dir];
    int n    = blockIdx.x;
    int b    = threadIdx.x >> 5;
    int lane = threadIdx.x & 31;
    int beg = off[n], end = off[n + 1];
    int inoff = s_in * 64 + lane * 2;
    float2 acc = make_float2(0.f, 0.f);
    int j = beg;
    int n4 = beg + ((end - beg) & ~3);
    for (; j < n4; j += 4) {
        int m0 = nbr[j], m1 = nbr[j+1], m2 = nbr[j+2], m3 = nbr[j+3];
        float w0 = wgt[j], w1 = wgt[j+1], w2 = wgt[j+2], w3 = wgt[j+3];
        float2 v0 = *(const float2*)(buf + (m0*BB + b)*PART + inoff);
        float2 v1 = *(const float2*)(buf + (m1*BB + b)*PART + inoff);
        float2 v2 = *(const float2*)(buf + (m2*BB + b)*PART + inoff);
        float2 v3 = *(const float2*)(buf + (m3*BB + b)*PART + inoff);
        acc.x += w0*v0.x + w1*v1.x + w2*v2.x + w3*v3.x;
        acc.y += w0*v0.y + w1*v1.y + w2*v2.y + w3*v3.y;
    }
    for (; j < end; j++) {
        int m = nbr[j]; float w = wgt[j];
        float2 v = *(const float2*)(buf + (m*BB + b)*PART + inoff);
        acc.x += w * v.x; acc.y += w * v.y;
    }
    int orow = (n * BB + b) * PART;
    float2 res = acc;
    if (cheb) {
        float2 p = *(const float2*)(buf + orow + s_prev * 64 + lane * 2);
        res.x = 2.f * acc.x - p.x;
        res.y = 2.f * acc.y - p.y;
    }
    *(float2*)(buf + orow + s_out * 64 + lane * 2) = res;
}

// ---------------- GEMMs ----------------
// Z|R: [80000 x 640] @ [640 x 128]; A row = (vx row | vh row)
__global__ void __launch_bounds__(256) k_gemm_zr(const float* __restrict__ bz,
                                                 const float* __restrict__ br) {
    __shared__ __align__(16) float As[128][33];
    __shared__ __align__(16) float Bs[32][128];
    int tid = threadIdx.x;
    int tx = tid & 15;
    int ty = tid >> 4;
    int rowBase = blockIdx.x * 128;

    unsigned long long acc[8][4];
#pragma unroll
    for (int i = 0; i < 8; i++)
#pragma unroll
        for (int j = 0; j < 4; j++) acc[i][j] = 0ull;

    for (int kk = 0; kk < 20; kk++) {
        const float* Asrc = (kk < 10) ? g_vx : g_vh;
        int soff = (kk < 10 ? kk : kk - 10) * 32;
#pragma unroll
        for (int t = 0; t < 4; t++) {
            int id = tid + t * 256;
            int r = id >> 3, c4 = id & 7;
            float4 v = *(const float4*)(Asrc + (rowBase + r) * PART + soff + c4 * 4);
            As[r][c4*4+0] = v.x; As[r][c4*4+1] = v.y; As[r][c4*4+2] = v.z; As[r][c4*4+3] = v.w;
        }
#pragma unroll
        for (int t = 0; t < 4; t++) {
            int id = tid + t * 256;
            int kr = id >> 5, c4 = id & 31;
            *(float4*)&Bs[kr][c4 * 4] = *(const float4*)(g_WZR + (kk * 32 + kr) * 128 + c4 * 4);
        }
        __syncthreads();
#pragma unroll
        for (int k = 0; k < 32; k++) {
            ulonglong2 b01 = *(const ulonglong2*)&Bs[k][tx * 8];
            ulonglong2 b23 = *(const ulonglong2*)&Bs[k][tx * 8 + 4];
#pragma unroll
            for (int i = 0; i < 8; i++) {
                unsigned long long ad = dup2(As[ty * 8 + i][k]);
                ffma2(acc[i][0], ad, b01.x);
                ffma2(acc[i][1], ad, b01.y);
                ffma2(acc[i][2], ad, b23.x);
                ffma2(acc[i][3], ad, b23.y);
            }
        }
        __syncthreads();
    }

    int cbase = tx * 8;
#pragma unroll
    for (int i = 0; i < 8; i++) {
        int g = rowBase + ty * 8 + i;
#pragma unroll
        for (int j = 0; j < 4; j++) {
            float v0, v1; unpack2(acc[i][j], v0, v1);
            int c0 = cbase + j * 2, c1 = c0 + 1;
            if (cbase < 64) {
                g_z[g * HH + c0] = sigm(v0 + bz[c0]);
                g_z[g * HH + c1] = sigm(v1 + bz[c1]);
            } else {
                int cc0 = c0 - 64, cc1 = c1 - 64;
                g_vr[g * PART + cc0] = sigm(v0 + br[cc0]) * g_vh[g * PART + cc0];
                g_vr[g * PART + cc1] = sigm(v1 + br[cc1]) * g_vh[g * PART + cc1];
            }
        }
    }
}

// H: [80000 x 640] @ [640 x 64]; A row = (vx row | vr row). GRU update -> vx slot0
__global__ void __launch_bounds__(128) k_gemm_h(const float* __restrict__ bh) {
    __shared__ __align__(16) float As[128][33];
    __shared__ __align__(16) float Bs[32][64];
    int tid = threadIdx.x;
    int tx = tid & 7;
    int ty = tid >> 3;
    int rowBase = blockIdx.x * 128;

    unsigned long long acc[8][4];
#pragma unroll
    for (int i = 0; i < 8; i++)
#pragma unroll
        for (int j = 0; j < 4; j++) acc[i][j] = 0ull;

    for (int kk = 0; kk < 20; kk++) {
        const float* Asrc = (kk < 10) ? g_vx : g_vr;
        int soff = (kk < 10 ? kk : kk - 10) * 32;
#pragma unroll
        for (int t = 0; t < 8; t++) {
            int id = tid + t * 128;
            int r = id >> 3, c4 = id & 7;
            float4 v = *(const float4*)(Asrc + (rowBase + r) * PART + soff + c4 * 4);
            As[r][c4*4+0] = v.x; As[r][c4*4+1] = v.y; As[r][c4*4+2] = v.z; As[r][c4*4+3] = v.w;
        }
#pragma unroll
        for (int t = 0; t < 4; t++) {
            int id = tid + t * 128;
            int kr = id >> 4, c4 = id & 15;
            *(float4*)&Bs[kr][c4 * 4] = *(const float4*)(g_WH + (kk * 32 + kr) * 64 + c4 * 4);
        }
        __syncthreads();
#pragma unroll
        for (int k = 0; k < 32; k++) {
            ulonglong2 b01 = *(const ulonglong2*)&Bs[k][tx * 8];
            ulonglong2 b23 = *(const ulonglong2*)&Bs[k][tx * 8 + 4];
#pragma unroll
            for (int i = 0; i < 8; i++) {
                unsigned long long ad = dup2(As[ty * 8 + i][k]);
                ffma2(acc[i][0], ad, b01.x);
                ffma2(acc[i][1], ad, b01.y);
                ffma2(acc[i][2], ad, b23.x);
                ffma2(acc[i][3], ad, b23.y);
            }
        }
        __syncthreads();
    }

    int cbase = tx * 8;
#pragma unroll
    for (int i = 0; i < 8; i++) {
        int g = rowBase + ty * 8 + i;
#pragma unroll
        for (int j = 0; j < 4; j++) {
            float v0, v1; unpack2(acc[i][j], v0, v1);
            int c0 = cbase + j * 2, c1 = c0 + 1;
            float ht0 = tanhf(v0 + bh[c0]);
            float ht1 = tanhf(v1 + bh[c1]);
            float z0 = g_z[g * HH + c0], z1 = g_z[g * HH + c1];
            float h0 = g_vh[g * PART + c0], h1 = g_vh[g * PART + c1];
            g_vx[g * PART + c0] = z0 * h0 + (1.f - z0) * ht0;
            g_vx[g * PART + c1] = z1 * h1 + (1.f - z1) * ht1;
        }
    }
}

// ---------------- projection ----------------
__global__ void __launch_bounds__(256) k_proj(const float* __restrict__ pw,
                                              const float* __restrict__ pb,
                                              float* __restrict__ out) {
    __shared__ float Ws[64 * 32];
    __shared__ float Bsh[32];
    int tid = threadIdx.x;
    for (int i = tid; i < 64 * 32; i += 256) Ws[i] = pw[i];
    if (tid < 32) Bsh[tid] = pb[tid];
    __syncthreads();
    int w = tid >> 5, lane = tid & 31;
    int g = blockIdx.x * 8 + w;
    const float* x = g_vx + g * PART;
    float xv0 = x[lane], xv1 = x[32 + lane];
    float acc = Bsh[lane];
#pragma unroll
    for (int f = 0; f < 32; f++)
        acc += __shfl_sync(0xffffffffu, xv0, f) * Ws[f * 32 + lane];
#pragma unroll
    for (int f = 0; f < 32; f++)
        acc += __shfl_sync(0xffffffffu, xv1, f) * Ws[(32 + f) * 32 + lane];
    int n = g >> 3, b = g & 7;
    out[(b * NN + n) * 32 + lane] = acc;
}

// ---------------- launch ----------------
extern "C" void kernel_launch(void* const* d_in, const int* in_sizes, int n_in,
                              void* d_out, int out_size) {
    (void)in_sizes; (void)n_in; (void)out_size;
    const float* ew = (const float*)d_in[0];
    const float* hs = (const float*)d_in[1];
    const float* go = (const float*)d_in[2];
    const float* Wz = (const float*)d_in[3];
    const float* bz = (const float*)d_in[4];
    const float* Wr = (const float*)d_in[5];
    const float* br = (const float*)d_in[6];
    const float* Wh = (const float*)d_in[7];
    const float* bh = (const float*)d_in[8];
    const float* pw = (const float*)d_in[9];
    const float* pb = (const float*)d_in[10];
    const int*   ei = (const int*)d_in[11];
    float* out = (float*)d_out;

    k_zero  <<<(NN + 255) / 256, 256>>>();
    k_degcnt<<<(EE + 255) / 256, 256>>>(ew, ei);
    k_scan  <<<2, 1024>>>();
    k_fill  <<<(EE + 255) / 256, 256>>>(ew, ei);
    k_init_x<<<(NB * HH + 255) / 256, 256>>>(go);

    dim3 g2(NN, 2), g1(NN, 1);
    for (int l = 0; l < 2; l++) {
        k_load_h   <<<(NB * HH + 255) / 256, 256>>>(hs, l);
        k_build_wzr<<<(640 * 128 + 255) / 256, 256>>>(Wz, Wr, l);
        k_build_wh <<<(640 * 64  + 255) / 256, 256>>>(Wh, l);

        // props on vx (buf 0) and vh (buf 1), batched via grid.y
        k_prop<<<g2, 256>>>(0, 1, 0, 1, 0, 0, 0);   // slot1 = A_f(slot0)
        k_prop<<<g2, 256>>>(0, 1, 0, 2, 0, 0, 1);   // slot2 = A_r(slot0)
        k_prop<<<g2, 256>>>(0, 1, 1, 3, 1, 0, 0);   // slot3 = 2 A_f(slot1) - slot0
        k_prop<<<g2, 256>>>(0, 1, 2, 4, 1, 0, 1);   // slot4 = 2 A_r(slot2) - slot0

        k_gemm_zr<<<625, 256>>>(bz + l * HH, br + l * HH);  // -> g_z, g_vr slot0 = R*h

        // props on vr (buf 2)
        k_prop<<<g1, 256>>>(2, 2, 0, 1, 0, 0, 0);
        k_prop<<<g1, 256>>>(2, 2, 0, 2, 0, 0, 1);
        k_prop<<<g1, 256>>>(2, 2, 1, 3, 1, 0, 0);
        k_prop<<<g1, 256>>>(2, 2, 2, 4, 1, 0, 1);

        k_gemm_h<<<625, 128>>>(bh + l * HH);        // -> new h into vx slot0
    }

    k_proj<<<NB / 8, 256>>>(pw, pb, out);
}

// round 4
// speedup vs baseline: 1.0758x; 1.0758x over previous
#include <cuda_runtime.h>

#define NN   10000
#define EE   160000
#define BB   8
#define HH   64
#define PART 320            // 5 slots * 64 features per (node,batch) row
#define NB   (NN*BB)        // 80000

// ---------------- device scratch ----------------
__device__ float g_deg_out[NN];
__device__ float g_deg_in[NN];
__device__ int   g_cnt[2][NN];
__device__ int   g_off[2][NN+1];
__device__ int   g_cur[2][NN];
__device__ int   g_nbr[2][EE];
__device__ float g_wgt[2][EE];

__device__ float g_vx[NB*PART];   // x-part slots: 0=x 1=A_f x 2=A_r x 3=cheb_f 4=cheb_r
__device__ float g_vh[NB*PART];   // h-part slots
__device__ float g_vr[NB*PART];   // (R*h)-part slots
__device__ float g_z [NB*HH];     // Z gate
__device__ float g_WZR[2*640*128];  // concat weights for Z|R gemm, per layer
__device__ float g_WH [2*640*64];   // concat weights for H gemm, per layer

// ---------------- packed f32x2 helpers ----------------
__device__ __forceinline__ void ffma2(unsigned long long &acc,
                                      unsigned long long a,
                                      unsigned long long b) {
    asm("fma.rn.f32x2 %0, %1, %2, %0;" : "+l"(acc) : "l"(a), "l"(b));
}
__device__ __forceinline__ unsigned long long dup2(float a) {
    unsigned long long r;
    asm("mov.b64 %0, {%1, %1};" : "=l"(r) : "r"(__float_as_uint(a)));
    return r;
}
__device__ __forceinline__ void unpack2(unsigned long long v, float &lo, float &hi) {
    unsigned l, h;
    asm("mov.b64 {%0, %1}, %2;" : "=r"(l), "=r"(h) : "l"(v));
    lo = __uint_as_float(l); hi = __uint_as_float(h);
}
__device__ __forceinline__ float sigm(float x) { return 1.f / (1.f + __expf(-x)); }

__device__ __forceinline__ float* partbuf(int id) {
    return id == 0 ? g_vx : (id == 1 ? g_vh : g_vr);
}

// ---------------- setup ----------------
__global__ void k_zero() {
    int i = blockIdx.x * 256 + threadIdx.x;
    if (i < NN) {
        g_deg_out[i] = 0.f; g_deg_in[i] = 0.f;
        g_cnt[0][i] = 0;    g_cnt[1][i] = 0;
    }
}

__global__ void k_degcnt(const float* __restrict__ ew, const int* __restrict__ ei) {
    int e = blockIdx.x * 256 + threadIdx.x;
    if (e >= EE) return;
    int s = ei[e], d = ei[EE + e];
    float w = ew[e];
    atomicAdd(&g_deg_out[s], w);
    atomicAdd(&g_deg_in[d],  w);
    atomicAdd(&g_cnt[0][d], 1);   // fwd CSR keyed by dst
    atomicAdd(&g_cnt[1][s], 1);   // rev CSR keyed by src
}

__global__ void k_scan() {   // grid=2, block=1024
    int d = blockIdx.x;
    __shared__ int sums[1024];
    int t = threadIdx.x;
    const int CH = 10;
    int base = t * CH;
    int s = 0;
    for (int i = 0; i < CH; i++) { int idx = base + i; if (idx < NN) s += g_cnt[d][idx]; }
    sums[t] = s; __syncthreads();
    for (int off = 1; off < 1024; off <<= 1) {
        int v = (t >= off) ? sums[t - off] : 0;
        __syncthreads();
        sums[t] += v;
        __syncthreads();
    }
    int run = (t == 0) ? 0 : sums[t - 1];
    for (int i = 0; i < CH; i++) {
        int idx = base + i;
        if (idx < NN) { g_off[d][idx] = run; g_cur[d][idx] = run; run += g_cnt[d][idx]; }
    }
    if (t == 1023) g_off[d][NN] = run;
}

__global__ void k_fill(const float* __restrict__ ew, const int* __restrict__ ei) {
    int e = blockIdx.x * 256 + threadIdx.x;
    if (e >= EE) return;
    int s = ei[e], d = ei[EE + e];
    float w = ew[e];
    float wo = g_deg_out[s]; float nout = w / (wo > 0.f ? wo : 1.f);
    float wi = g_deg_in[d];  float nin  = w / (wi > 0.f ? wi : 1.f);
    int p = atomicAdd(&g_cur[0][d], 1); g_nbr[0][p] = s; g_wgt[0][p] = nout;
    int q = atomicAdd(&g_cur[1][s], 1); g_nbr[1][q] = d; g_wgt[1][q] = nin;
}

__global__ void k_init_x(const float* __restrict__ go) {
    int t = blockIdx.x * 256 + threadIdx.x;
    if (t >= NB * HH) return;
    int f = t & 63; int rest = t >> 6;
    int n = rest % NN; int b = rest / NN;
    g_vx[(n * BB + b) * PART + f] = go[t];
}

__global__ void k_load_h(const float* __restrict__ hs, int l) {
    int t = blockIdx.x * 256 + threadIdx.x;
    if (t >= NB * HH) return;
    int f = t & 63; int rest = t >> 6;
    int n = rest % NN; int b = rest / NN;
    g_vh[(n * BB + b) * PART + f] = hs[(size_t)l * NB * HH + t];
}

// W layout [L,2,K,128,64]. Slots: 0:(dir0+dir1,k0) 1:(0,k1) 2:(1,k1) 3:(0,k2) 4:(1,k2)
__device__ __forceinline__ float wslot(const float* W, int l, int s, int wrow, int o) {
    if (s == 0) {
        return W[((((l*2+0)*3+0)*128 + wrow)*64) + o] +
               W[((((l*2+1)*3+0)*128 + wrow)*64) + o];
    }
    int dir = (s == 1 || s == 3) ? 0 : 1;
    int k   = (s <= 2) ? 1 : 2;
    return W[((((l*2+dir)*3+k)*128 + wrow)*64) + o];
}

__global__ void k_build_wzr(const float* __restrict__ Wz, const float* __restrict__ Wr) {
    int idx = blockIdx.x * 256 + threadIdx.x;
    if (idx >= 2 * 640 * 128) return;
    int l = idx >= 640 * 128 ? 1 : 0;
    int li = idx - l * 640 * 128;
    int j = li >> 7, c = li & 127;
    int p = j / 320, s = (j % 320) / 64, f = j & 63;
    int wrow = p * 64 + f;
    const float* W = (c < 64) ? Wz : Wr;
    g_WZR[l * 640 * 128 + j * 128 + c] = wslot(W, l, s, wrow, c & 63);
}

__global__ void k_build_wh(const float* __restrict__ Wh) {
    int idx = blockIdx.x * 256 + threadIdx.x;
    if (idx >= 2 * 640 * 64) return;
    int l = idx >= 640 * 64 ? 1 : 0;
    int li = idx - l * 640 * 64;
    int j = li >> 6, o = li & 63;
    int p = j / 320, s = (j % 320) / 64, f = j & 63;
    g_WH[l * 640 * 64 + j * 64 + o] = wslot(Wh, l, s, p * 64 + f, o);
}

// ---------------- propagation v2 ----------------
// grid: (NN, nbuf, 2 dirs); block 128: warp = 2 batches, 16 lanes * float4 = 64 feats
__global__ void __launch_bounds__(128) k_prop2(int bufA, int bufB,
                                               int s_in_f, int s_out_f,
                                               int s_in_r, int s_out_r,
                                               int cheb, int s_prev) {
    int dir = blockIdx.z;
    float* buf = partbuf(blockIdx.y == 0 ? bufA : bufB);
    const int*   off = g_off[dir];
    const int*   nbr = g_nbr[dir];
    const float* wgt = g_wgt[dir];
    int s_in  = dir ? s_in_r  : s_in_f;
    int s_out = dir ? s_out_r : s_out_f;
    int n    = blockIdx.x;
    int w    = threadIdx.x >> 5;
    int lane = threadIdx.x & 31;
    int b    = w * 2 + (lane >> 4);
    int fo   = (lane & 15) * 4;        // float offset within 64
    int beg = off[n], end = off[n + 1];
    int inoff = s_in * 64 + fo;
    float4 acc = make_float4(0.f, 0.f, 0.f, 0.f);
    int j = beg;
    int e8 = beg + ((end - beg) & ~7);
    for (; j < e8; j += 8) {
#pragma unroll
        for (int u = 0; u < 8; u++) {
            int   m = __ldg(&nbr[j + u]);
            float ww = __ldg(&wgt[j + u]);
            float4 v = *(const float4*)(buf + (m * BB + b) * PART + inoff);
            acc.x += ww * v.x; acc.y += ww * v.y;
            acc.z += ww * v.z; acc.w += ww * v.w;
        }
    }
    for (; j < end; j++) {
        int   m = __ldg(&nbr[j]);
        float ww = __ldg(&wgt[j]);
        float4 v = *(const float4*)(buf + (m * BB + b) * PART + inoff);
        acc.x += ww * v.x; acc.y += ww * v.y;
        acc.z += ww * v.z; acc.w += ww * v.w;
    }
    int orow = (n * BB + b) * PART;
    float4 res = acc;
    if (cheb) {
        float4 p = *(const float4*)(buf + orow + s_prev * 64 + fo);
        res.x = 2.f * acc.x - p.x; res.y = 2.f * acc.y - p.y;
        res.z = 2.f * acc.z - p.z; res.w = 2.f * acc.w - p.w;
    }
    *(float4*)(buf + orow + s_out * 64 + fo) = res;
}

// ---------------- GEMMs (k-major smem A, f32x2 FMA) ----------------
// Z|R: [80000 x 640] @ [640 x 128]; A row = (vx row | vh row)
__global__ void __launch_bounds__(256) k_gemm_zr(int l,
                                                 const float* __restrict__ bz,
                                                 const float* __restrict__ br) {
    __shared__ __align__(16) float As[32][132];   // k-major, padded
    __shared__ __align__(16) float Bs[32][128];
    const float* W = g_WZR + l * 640 * 128;
    int tid = threadIdx.x;
    int tx = tid & 15;      // col block: tx*8
    int ty = tid >> 4;      // row block: ty*8
    int rowBase = blockIdx.x * 128;

    unsigned long long acc[8][4];
#pragma unroll
    for (int i = 0; i < 8; i++)
#pragma unroll
        for (int j = 0; j < 4; j++) acc[i][j] = 0ull;

    for (int kk = 0; kk < 20; kk++) {
        const float* Asrc = (kk < 10) ? g_vx : g_vh;
        int soff = (kk < 10 ? kk : kk - 10) * 32;
#pragma unroll
        for (int t = 0; t < 4; t++) {       // A: 128 rows x 32 k, transpose on store
            int id = tid + t * 256;
            int r = id >> 3, c4 = id & 7;
            float4 v = *(const float4*)(Asrc + (rowBase + r) * PART + soff + c4 * 4);
            int kb = c4 * 4;
            As[kb + 0][r] = v.x; As[kb + 1][r] = v.y;
            As[kb + 2][r] = v.z; As[kb + 3][r] = v.w;
        }
#pragma unroll
        for (int t = 0; t < 4; t++) {       // B: 32x128
            int id = tid + t * 256;
            int kr = id >> 5, c4 = id & 31;
            *(float4*)&Bs[kr][c4 * 4] = *(const float4*)(W + (kk * 32 + kr) * 128 + c4 * 4);
        }
        __syncthreads();
#pragma unroll
        for (int k = 0; k < 32; k++) {
            float4 a0 = *(const float4*)&As[k][ty * 8];
            float4 a1 = *(const float4*)&As[k][ty * 8 + 4];
            ulonglong2 b01 = *(const ulonglong2*)&Bs[k][tx * 8];
            ulonglong2 b23 = *(const ulonglong2*)&Bs[k][tx * 8 + 4];
            unsigned long long ad;
            ad = dup2(a0.x);
            ffma2(acc[0][0], ad, b01.x); ffma2(acc[0][1], ad, b01.y);
            ffma2(acc[0][2], ad, b23.x); ffma2(acc[0][3], ad, b23.y);
            ad = dup2(a0.y);
            ffma2(acc[1][0], ad, b01.x); ffma2(acc[1][1], ad, b01.y);
            ffma2(acc[1][2], ad, b23.x); ffma2(acc[1][3], ad, b23.y);
            ad = dup2(a0.z);
            ffma2(acc[2][0], ad, b01.x); ffma2(acc[2][1], ad, b01.y);
            ffma2(acc[2][2], ad, b23.x); ffma2(acc[2][3], ad, b23.y);
            ad = dup2(a0.w);
            ffma2(acc[3][0], ad, b01.x); ffma2(acc[3][1], ad, b01.y);
            ffma2(acc[3][2], ad, b23.x); ffma2(acc[3][3], ad, b23.y);
            ad = dup2(a1.x);
            ffma2(acc[4][0], ad, b01.x); ffma2(acc[4][1], ad, b01.y);
            ffma2(acc[4][2], ad, b23.x); ffma2(acc[4][3], ad, b23.y);
            ad = dup2(a1.y);
            ffma2(acc[5][0], ad, b01.x); ffma2(acc[5][1], ad, b01.y);
            ffma2(acc[5][2], ad, b23.x); ffma2(acc[5][3], ad, b23.y);
            ad = dup2(a1.z);
            ffma2(acc[6][0], ad, b01.x); ffma2(acc[6][1], ad, b01.y);
            ffma2(acc[6][2], ad, b23.x); ffma2(acc[6][3], ad, b23.y);
            ad = dup2(a1.w);
            ffma2(acc[7][0], ad, b01.x); ffma2(acc[7][1], ad, b01.y);
            ffma2(acc[7][2], ad, b23.x); ffma2(acc[7][3], ad, b23.y);
        }
        __syncthreads();
    }

    int cbase = tx * 8;
#pragma unroll
    for (int i = 0; i < 8; i++) {
        int g = rowBase + ty * 8 + i;
#pragma unroll
        for (int j = 0; j < 4; j++) {
            float v0, v1; unpack2(acc[i][j], v0, v1);
            int c0 = cbase + j * 2, c1 = c0 + 1;
            if (cbase < 64) {
                g_z[g * HH + c0] = sigm(v0 + __ldg(&bz[c0]));
                g_z[g * HH + c1] = sigm(v1 + __ldg(&bz[c1]));
            } else {
                int cc0 = c0 - 64, cc1 = c1 - 64;
                g_vr[g * PART + cc0] = sigm(v0 + __ldg(&br[cc0])) * g_vh[g * PART + cc0];
                g_vr[g * PART + cc1] = sigm(v1 + __ldg(&br[cc1])) * g_vh[g * PART + cc1];
            }
        }
    }
}

// H: [80000 x 640] @ [640 x 64]; A row = (vx row | vr row). GRU update -> vx slot0
__global__ void __launch_bounds__(256) k_gemm_h(int l, const float* __restrict__ bh) {
    __shared__ __align__(16) float As[32][132];
    __shared__ __align__(16) float Bs[32][64];
    const float* W = g_WH + l * 640 * 64;
    int tid = threadIdx.x;
    int tx = tid & 7;       // cols tx*8
    int ty = tid >> 3;      // rows ty*4 (0..31)
    int rowBase = blockIdx.x * 128;

    unsigned long long acc[4][4];
#pragma unroll
    for (int i = 0; i < 4; i++)
#pragma unroll
        for (int j = 0; j < 4; j++) acc[i][j] = 0ull;

    for (int kk = 0; kk < 20; kk++) {
        const float* Asrc = (kk < 10) ? g_vx : g_vr;
        int soff = (kk < 10 ? kk : kk - 10) * 32;
#pragma unroll
        for (int t = 0; t < 4; t++) {
            int id = tid + t * 256;
            int r = id >> 3, c4 = id & 7;
            float4 v = *(const float4*)(Asrc + (rowBase + r) * PART + soff + c4 * 4);
            int kb = c4 * 4;
            As[kb + 0][r] = v.x; As[kb + 1][r] = v.y;
            As[kb + 2][r] = v.z; As[kb + 3][r] = v.w;
        }
#pragma unroll
        for (int t = 0; t < 2; t++) {       // B: 32x64 = 512 float4
            int id = tid + t * 256;
            int kr = id >> 4, c4 = id & 15;
            *(float4*)&Bs[kr][c4 * 4] = *(const float4*)(W + (kk * 32 + kr) * 64 + c4 * 4);
        }
        __syncthreads();
#pragma unroll
        for (int k = 0; k < 32; k++) {
            float4 a0 = *(const float4*)&As[k][ty * 4];
            ulonglong2 b01 = *(const ulonglong2*)&Bs[k][tx * 8];
            ulonglong2 b23 = *(const ulonglong2*)&Bs[k][tx * 8 + 4];
            unsigned long long ad;
            ad = dup2(a0.x);
            ffma2(acc[0][0], ad, b01.x); ffma2(acc[0][1], ad, b01.y);
            ffma2(acc[0][2], ad, b23.x); ffma2(acc[0][3], ad, b23.y);
            ad = dup2(a0.y);
            ffma2(acc[1][0], ad, b01.x); ffma2(acc[1][1], ad, b01.y);
            ffma2(acc[1][2], ad, b23.x); ffma2(acc[1][3], ad, b23.y);
            ad = dup2(a0.z);
            ffma2(acc[2][0], ad, b01.x); ffma2(acc[2][1], ad, b01.y);
            ffma2(acc[2][2], ad, b23.x); ffma2(acc[2][3], ad, b23.y);
            ad = dup2(a0.w);
            ffma2(acc[3][0], ad, b01.x); ffma2(acc[3][1], ad, b01.y);
            ffma2(acc[3][2], ad, b23.x); ffma2(acc[3][3], ad, b23.y);
        }
        __syncthreads();
    }

    int cbase = tx * 8;
#pragma unroll
    for (int i = 0; i < 4; i++) {
        int g = rowBase + ty * 4 + i;
#pragma unroll
        for (int j = 0; j < 4; j++) {
            float v0, v1; unpack2(acc[i][j], v0, v1);
            int c0 = cbase + j * 2, c1 = c0 + 1;
            float ht0 = tanhf(v0 + __ldg(&bh[c0]));
            float ht1 = tanhf(v1 + __ldg(&bh[c1]));
            float z0 = g_z[g * HH + c0], z1 = g_z[g * HH + c1];
            float h0 = g_vh[g * PART + c0], h1 = g_vh[g * PART + c1];
            g_vx[g * PART + c0] = z0 * h0 + (1.f - z0) * ht0;
            g_vx[g * PART + c1] = z1 * h1 + (1.f - z1) * ht1;
        }
    }
}

// ---------------- projection ----------------
__global__ void __launch_bounds__(256) k_proj(const float* __restrict__ pw,
                                              const float* __restrict__ pb,
                                              float* __restrict__ out) {
    __shared__ float Ws[64 * 32];
    __shared__ float Bsh[32];
    int tid = threadIdx.x;
    for (int i = tid; i < 64 * 32; i += 256) Ws[i] = pw[i];
    if (tid < 32) Bsh[tid] = pb[tid];
    __syncthreads();
    int w = tid >> 5, lane = tid & 31;
    int g = blockIdx.x * 8 + w;
    const float* x = g_vx + g * PART;
    float xv0 = x[lane], xv1 = x[32 + lane];
    float acc = Bsh[lane];
#pragma unroll
    for (int f = 0; f < 32; f++)
        acc += __shfl_sync(0xffffffffu, xv0, f) * Ws[f * 32 + lane];
#pragma unroll
    for (int f = 0; f < 32; f++)
        acc += __shfl_sync(0xffffffffu, xv1, f) * Ws[(32 + f) * 32 + lane];
    int n = g >> 3, b = g & 7;
    out[(b * NN + n) * 32 + lane] = acc;
}

// ---------------- launch ----------------
extern "C" void kernel_launch(void* const* d_in, const int* in_sizes, int n_in,
                              void* d_out, int out_size) {
    (void)in_sizes; (void)n_in; (void)out_size;
    const float* ew = (const float*)d_in[0];
    const float* hs = (const float*)d_in[1];
    const float* go = (const float*)d_in[2];
    const float* Wz = (const float*)d_in[3];
    const float* bz = (const float*)d_in[4];
    const float* Wr = (const float*)d_in[5];
    const float* br = (const float*)d_in[6];
    const float* Wh = (const float*)d_in[7];
    const float* bh = (const float*)d_in[8];
    const float* pw = (const float*)d_in[9];
    const float* pb = (const float*)d_in[10];
    const int*   ei = (const int*)d_in[11];
    float* out = (float*)d_out;

    k_zero  <<<(NN + 255) / 256, 256>>>();
    k_degcnt<<<(EE + 255) / 256, 256>>>(ew, ei);
    k_scan  <<<2, 1024>>>();
    k_fill  <<<(EE + 255) / 256, 256>>>(ew, ei);
    k_init_x<<<(NB * HH + 255) / 256, 256>>>(go);
    k_build_wzr<<<(2 * 640 * 128 + 255) / 256, 256>>>(Wz, Wr);
    k_build_wh <<<(2 * 640 * 64  + 255) / 256, 256>>>(Wh);

    dim3 g2(NN, 2, 2), g1(NN, 1, 2);
    for (int l = 0; l < 2; l++) {
        k_load_h<<<(NB * HH + 255) / 256, 256>>>(hs, l);

        // props on vx (buf 0) and vh (buf 1), both dirs in one launch
        k_prop2<<<g2, 128>>>(0, 1, 0, 1, 0, 2, 0, 0);   // slot1 = A_f s0; slot2 = A_r s0
        k_prop2<<<g2, 128>>>(0, 1, 1, 3, 2, 4, 1, 0);   // slot3/4 = 2 A(slot1/2) - s0

        k_gemm_zr<<<625, 256>>>(l, bz + l * HH, br + l * HH);

        // props on vr (buf 2)
        k_prop2<<<g1, 128>>>(2, 2, 0, 1, 0, 2, 0, 0);
        k_prop2<<<g1, 128>>>(2, 2, 1, 3, 2, 4, 1, 0);

        k_gemm_h<<<625, 256>>>(l, bh + l * HH);  // -> new h in vx slot0
    }

    k_proj<<<NB / 8, 256>>>(pw, pb, out);
}

// round 5
// speedup vs baseline: 1.4816x; 1.3772x over previous
#include <cuda_runtime.h>

#define NN   10000
#define EE   160000
#define BB   8
#define HH   64
#define PART 320            // 5 slots * 64 features per (node,batch) row
#define NB   (NN*BB)        // 80000

// ---------------- device scratch ----------------
__device__ float g_deg_out[NN];
__device__ float g_deg_in[NN];
__device__ int   g_cnt[2][NN];
__device__ int   g_off[2][NN+1];
__device__ int   g_cur[2][NN];
__device__ int   g_nbr[2][EE];
__device__ float g_wgt[2][EE];

__device__ float g_vx[NB*PART];   // x-part slots: 0=x 1=A_f x 2=A_r x 3=cheb_f 4=cheb_r
__device__ float g_vh[NB*PART];   // h-part slots
__device__ float g_vr[NB*PART];   // (R*h)-part slots
__device__ float g_z [NB*HH];     // Z gate
__device__ float g_WZR[2*640*128];  // concat weights (tf32-rounded) for Z|R gemm
__device__ float g_WH [2*640*64];   // concat weights (tf32-rounded) for H gemm

// ---------------- helpers ----------------
__device__ __forceinline__ float sigm(float x) { return 1.f / (1.f + __expf(-x)); }

__device__ __forceinline__ float tf32r(float x) {
    unsigned u;
    asm("cvt.rna.tf32.f32 %0, %1;" : "=r"(u) : "f"(x));
    return __uint_as_float(u);
}

__device__ __forceinline__ void mma_tf32(float &c0, float &c1, float &c2, float &c3,
                                         unsigned a0, unsigned a1, unsigned a2, unsigned a3,
                                         unsigned b0, unsigned b1) {
    asm volatile(
        "mma.sync.aligned.m16n8k8.row.col.f32.tf32.tf32.f32 "
        "{%0,%1,%2,%3}, {%4,%5,%6,%7}, {%8,%9}, {%0,%1,%2,%3};"
        : "+f"(c0), "+f"(c1), "+f"(c2), "+f"(c3)
        : "r"(a0), "r"(a1), "r"(a2), "r"(a3), "r"(b0), "r"(b1));
}

__device__ __forceinline__ float* partbuf(int id) {
    return id == 0 ? g_vx : (id == 1 ? g_vh : g_vr);
}

// ---------------- setup ----------------
__global__ void k_zero() {
    int i = blockIdx.x * 256 + threadIdx.x;
    if (i < NN) {
        g_deg_out[i] = 0.f; g_deg_in[i] = 0.f;
        g_cnt[0][i] = 0;    g_cnt[1][i] = 0;
    }
}

__global__ void k_degcnt(const float* __restrict__ ew, const int* __restrict__ ei) {
    int e = blockIdx.x * 256 + threadIdx.x;
    if (e >= EE) return;
    int s = ei[e], d = ei[EE + e];
    float w = ew[e];
    atomicAdd(&g_deg_out[s], w);
    atomicAdd(&g_deg_in[d],  w);
    atomicAdd(&g_cnt[0][d], 1);
    atomicAdd(&g_cnt[1][s], 1);
}

__global__ void k_scan() {   // grid=2, block=1024
    int d = blockIdx.x;
    __shared__ int sums[1024];
    int t = threadIdx.x;
    const int CH = 10;
    int base = t * CH;
    int s = 0;
    for (int i = 0; i < CH; i++) { int idx = base + i; if (idx < NN) s += g_cnt[d][idx]; }
    sums[t] = s; __syncthreads();
    for (int off = 1; off < 1024; off <<= 1) {
        int v = (t >= off) ? sums[t - off] : 0;
        __syncthreads();
        sums[t] += v;
        __syncthreads();
    }
    int run = (t == 0) ? 0 : sums[t - 1];
    for (int i = 0; i < CH; i++) {
        int idx = base + i;
        if (idx < NN) { g_off[d][idx] = run; g_cur[d][idx] = run; run += g_cnt[d][idx]; }
    }
    if (t == 1023) g_off[d][NN] = run;
}

__global__ void k_fill(const float* __restrict__ ew, const int* __restrict__ ei) {
    int e = blockIdx.x * 256 + threadIdx.x;
    if (e >= EE) return;
    int s = ei[e], d = ei[EE + e];
    float w = ew[e];
    float wo = g_deg_out[s]; float nout = w / (wo > 0.f ? wo : 1.f);
    float wi = g_deg_in[d];  float nin  = w / (wi > 0.f ? wi : 1.f);
    int p = atomicAdd(&g_cur[0][d], 1); g_nbr[0][p] = s; g_wgt[0][p] = nout;
    int q = atomicAdd(&g_cur[1][s], 1); g_nbr[1][q] = d; g_wgt[1][q] = nin;
}

__global__ void k_init_x(const float* __restrict__ go) {
    int t = blockIdx.x * 256 + threadIdx.x;
    if (t >= NB * HH) return;
    int f = t & 63; int rest = t >> 6;
    int n = rest % NN; int b = rest / NN;
    g_vx[(n * BB + b) * PART + f] = go[t];
}

__global__ void k_load_h(const float* __restrict__ hs, int l) {
    int t = blockIdx.x * 256 + threadIdx.x;
    if (t >= NB * HH) return;
    int f = t & 63; int rest = t >> 6;
    int n = rest % NN; int b = rest / NN;
    g_vh[(n * BB + b) * PART + f] = hs[(size_t)l * NB * HH + t];
}

// W layout [L,2,K,128,64]. Slots: 0:(dir0+dir1,k0) 1:(0,k1) 2:(1,k1) 3:(0,k2) 4:(1,k2)
__device__ __forceinline__ float wslot(const float* W, int l, int s, int wrow, int o) {
    if (s == 0) {
        return W[((((l*2+0)*3+0)*128 + wrow)*64) + o] +
               W[((((l*2+1)*3+0)*128 + wrow)*64) + o];
    }
    int dir = (s == 1 || s == 3) ? 0 : 1;
    int k   = (s <= 2) ? 1 : 2;
    return W[((((l*2+dir)*3+k)*128 + wrow)*64) + o];
}

__global__ void k_build_wzr(const float* __restrict__ Wz, const float* __restrict__ Wr) {
    int idx = blockIdx.x * 256 + threadIdx.x;
    if (idx >= 2 * 640 * 128) return;
    int l = idx >= 640 * 128 ? 1 : 0;
    int li = idx - l * 640 * 128;
    int j = li >> 7, c = li & 127;
    int p = j / 320, s = (j % 320) / 64, f = j & 63;
    int wrow = p * 64 + f;
    const float* W = (c < 64) ? Wz : Wr;
    g_WZR[l * 640 * 128 + j * 128 + c] = tf32r(wslot(W, l, s, wrow, c & 63));
}

__global__ void k_build_wh(const float* __restrict__ Wh) {
    int idx = blockIdx.x * 256 + threadIdx.x;
    if (idx >= 2 * 640 * 64) return;
    int l = idx >= 640 * 64 ? 1 : 0;
    int li = idx - l * 640 * 64;
    int j = li >> 6, o = li & 63;
    int p = j / 320, s = (j % 320) / 64, f = j & 63;
    g_WH[l * 640 * 64 + j * 64 + o] = tf32r(wslot(Wh, l, s, p * 64 + f, o));
}

// ---------------- propagation ----------------
// grid: (NN, nbuf, 2 dirs); block 128: warp = 2 batches, 16 lanes * float4 = 64 feats
__global__ void __launch_bounds__(128) k_prop2(int bufA, int bufB,
                                               int s_in_f, int s_out_f,
                                               int s_in_r, int s_out_r,
                                               int cheb, int s_prev) {
    int dir = blockIdx.z;
    float* buf = partbuf(blockIdx.y == 0 ? bufA : bufB);
    const int*   off = g_off[dir];
    const int*   nbr = g_nbr[dir];
    const float* wgt = g_wgt[dir];
    int s_in  = dir ? s_in_r  : s_in_f;
    int s_out = dir ? s_out_r : s_out_f;
    int n    = blockIdx.x;
    int w    = threadIdx.x >> 5;
    int lane = threadIdx.x & 31;
    int b    = w * 2 + (lane >> 4);
    int fo   = (lane & 15) * 4;
    int beg = off[n], end = off[n + 1];
    int inoff = s_in * 64 + fo;
    float4 acc = make_float4(0.f, 0.f, 0.f, 0.f);
    int j = beg;
    int e8 = beg + ((end - beg) & ~7);
    for (; j < e8; j += 8) {
#pragma unroll
        for (int u = 0; u < 8; u++) {
            int   m = __ldg(&nbr[j + u]);
            float ww = __ldg(&wgt[j + u]);
            float4 v = *(const float4*)(buf + (m * BB + b) * PART + inoff);
            acc.x += ww * v.x; acc.y += ww * v.y;
            acc.z += ww * v.z; acc.w += ww * v.w;
        }
    }
    for (; j < end; j++) {
        int   m = __ldg(&nbr[j]);
        float ww = __ldg(&wgt[j]);
        float4 v = *(const float4*)(buf + (m * BB + b) * PART + inoff);
        acc.x += ww * v.x; acc.y += ww * v.y;
        acc.z += ww * v.z; acc.w += ww * v.w;
    }
    int orow = (n * BB + b) * PART;
    float4 res = acc;
    if (cheb) {
        float4 p = *(const float4*)(buf + orow + s_prev * 64 + fo);
        res.x = 2.f * acc.x - p.x; res.y = 2.f * acc.y - p.y;
        res.z = 2.f * acc.z - p.z; res.w = 2.f * acc.w - p.w;
    }
    *(float4*)(buf + orow + s_out * 64 + fo) = res;
}

// ---------------- tf32 tensor-core GEMMs ----------------
// Z|R: [80000 x 640] @ [640 x 128]; A row = (vx row | vh row)
// Block 256 = 8 warps, tile 128x128, warps 4x2 (32 rows x 64 cols each)
__global__ void __launch_bounds__(256) k_gemm_zr(int l,
                                                 const float* __restrict__ bz,
                                                 const float* __restrict__ br) {
    __shared__ float As[128][36];   // row-major A, tf32-rounded
    __shared__ float Bs[32][136];   // k-major B (pre-rounded)
    const float* W = g_WZR + l * 640 * 128;
    int tid = threadIdx.x;
    int wid = tid >> 5, lane = tid & 31;
    int warpM = wid & 3, warpN = wid >> 2;
    int g4 = lane >> 2, t4 = lane & 3;
    int rowBase = blockIdx.x * 128;

    float c[2][8][4];
#pragma unroll
    for (int mt = 0; mt < 2; mt++)
#pragma unroll
        for (int nt = 0; nt < 8; nt++)
#pragma unroll
            for (int i = 0; i < 4; i++) c[mt][nt][i] = 0.f;

    for (int kk = 0; kk < 20; kk++) {
        const float* Asrc = (kk < 10) ? g_vx : g_vh;
        int soff = (kk < 10 ? kk : kk - 10) * 32;
#pragma unroll
        for (int t = 0; t < 4; t++) {           // A: 128x32 = 1024 float4
            int id = tid + t * 256;
            int r = id >> 3, c4 = id & 7;
            float4 v = *(const float4*)(Asrc + (rowBase + r) * PART + soff + c4 * 4);
            int kb = c4 * 4;
            As[r][kb + 0] = tf32r(v.x); As[r][kb + 1] = tf32r(v.y);
            As[r][kb + 2] = tf32r(v.z); As[r][kb + 3] = tf32r(v.w);
        }
#pragma unroll
        for (int t = 0; t < 4; t++) {           // B: 32x128 = 1024 float4
            int id = tid + t * 256;
            int kr = id >> 5, c4 = id & 31;
            float4 v = *(const float4*)(W + (kk * 32 + kr) * 128 + c4 * 4);
            int cb = c4 * 4;
            Bs[kr][cb + 0] = v.x; Bs[kr][cb + 1] = v.y;
            Bs[kr][cb + 2] = v.z; Bs[kr][cb + 3] = v.w;
        }
        __syncthreads();
#pragma unroll
        for (int kc = 0; kc < 4; kc++) {
            int k0 = kc * 8;
            unsigned a[2][4];
#pragma unroll
            for (int mt = 0; mt < 2; mt++) {
                int rm = warpM * 32 + mt * 16;
                a[mt][0] = __float_as_uint(As[rm + g4][k0 + t4]);
                a[mt][1] = __float_as_uint(As[rm + g4 + 8][k0 + t4]);
                a[mt][2] = __float_as_uint(As[rm + g4][k0 + t4 + 4]);
                a[mt][3] = __float_as_uint(As[rm + g4 + 8][k0 + t4 + 4]);
            }
#pragma unroll
            for (int nt = 0; nt < 8; nt++) {
                int cn = warpN * 64 + nt * 8;
                unsigned b0 = __float_as_uint(Bs[k0 + t4][cn + g4]);
                unsigned b1 = __float_as_uint(Bs[k0 + t4 + 4][cn + g4]);
#pragma unroll
                for (int mt = 0; mt < 2; mt++)
                    mma_tf32(c[mt][nt][0], c[mt][nt][1], c[mt][nt][2], c[mt][nt][3],
                             a[mt][0], a[mt][1], a[mt][2], a[mt][3], b0, b1);
            }
        }
        __syncthreads();
    }

    // epilogue: warpN==0 -> Z gate; warpN==1 -> R gate * h
#pragma unroll
    for (int mt = 0; mt < 2; mt++) {
#pragma unroll
        for (int nt = 0; nt < 8; nt++) {
            int gr0 = rowBase + warpM * 32 + mt * 16 + g4;
            int cv  = nt * 8 + 2 * t4;                 // column within 64
            if (warpN == 0) {
                float bz0 = __ldg(&bz[cv]), bz1 = __ldg(&bz[cv + 1]);
                g_z[gr0 * HH + cv]           = sigm(c[mt][nt][0] + bz0);
                g_z[gr0 * HH + cv + 1]       = sigm(c[mt][nt][1] + bz1);
                g_z[(gr0 + 8) * HH + cv]     = sigm(c[mt][nt][2] + bz0);
                g_z[(gr0 + 8) * HH + cv + 1] = sigm(c[mt][nt][3] + bz1);
            } else {
                float br0 = __ldg(&br[cv]), br1 = __ldg(&br[cv + 1]);
                g_vr[gr0 * PART + cv]           = sigm(c[mt][nt][0] + br0) * g_vh[gr0 * PART + cv];
                g_vr[gr0 * PART + cv + 1]       = sigm(c[mt][nt][1] + br1) * g_vh[gr0 * PART + cv + 1];
                g_vr[(gr0 + 8) * PART + cv]     = sigm(c[mt][nt][2] + br0) * g_vh[(gr0 + 8) * PART + cv];
                g_vr[(gr0 + 8) * PART + cv + 1] = sigm(c[mt][nt][3] + br1) * g_vh[(gr0 + 8) * PART + cv + 1];
            }
        }
    }
}

// H: [80000 x 640] @ [640 x 64]; A row = (vx row | vr row). GRU update -> vx slot0
// Block 256 = 8 warps, tile 128x64, each warp 16 rows x 64 cols
__global__ void __launch_bounds__(256) k_gemm_h(int l, const float* __restrict__ bh) {
    __shared__ float As[128][36];
    __shared__ float Bs[32][72];
    const float* W = g_WH + l * 640 * 64;
    int tid = threadIdx.x;
    int wid = tid >> 5, lane = tid & 31;
    int g4 = lane >> 2, t4 = lane & 3;
    int rowBase = blockIdx.x * 128;

    float c[8][4];
#pragma unroll
    for (int nt = 0; nt < 8; nt++)
#pragma unroll
        for (int i = 0; i < 4; i++) c[nt][i] = 0.f;

    for (int kk = 0; kk < 20; kk++) {
        const float* Asrc = (kk < 10) ? g_vx : g_vr;
        int soff = (kk < 10 ? kk : kk - 10) * 32;
#pragma unroll
        for (int t = 0; t < 4; t++) {           // A: 1024 float4
            int id = tid + t * 256;
            int r = id >> 3, c4 = id & 7;
            float4 v = *(const float4*)(Asrc + (rowBase + r) * PART + soff + c4 * 4);
            int kb = c4 * 4;
            As[r][kb + 0] = tf32r(v.x); As[r][kb + 1] = tf32r(v.y);
            As[r][kb + 2] = tf32r(v.z); As[r][kb + 3] = tf32r(v.w);
        }
#pragma unroll
        for (int t = 0; t < 2; t++) {           // B: 32x64 = 512 float4
            int id = tid + t * 256;
            int kr = id >> 4, c4 = id & 15;
            float4 v = *(const float4*)(W + (kk * 32 + kr) * 64 + c4 * 4);
            int cb = c4 * 4;
            Bs[kr][cb + 0] = v.x; Bs[kr][cb + 1] = v.y;
            Bs[kr][cb + 2] = v.z; Bs[kr][cb + 3] = v.w;
        }
        __syncthreads();
#pragma unroll
        for (int kc = 0; kc < 4; kc++) {
            int k0 = kc * 8;
            int rm = wid * 16;
            unsigned a0 = __float_as_uint(As[rm + g4][k0 + t4]);
            unsigned a1 = __float_as_uint(As[rm + g4 + 8][k0 + t4]);
            unsigned a2 = __float_as_uint(As[rm + g4][k0 + t4 + 4]);
            unsigned a3 = __float_as_uint(As[rm + g4 + 8][k0 + t4 + 4]);
#pragma unroll
            for (int nt = 0; nt < 8; nt++) {
                int cn = nt * 8;
                unsigned b0 = __float_as_uint(Bs[k0 + t4][cn + g4]);
                unsigned b1 = __float_as_uint(Bs[k0 + t4 + 4][cn + g4]);
                mma_tf32(c[nt][0], c[nt][1], c[nt][2], c[nt][3], a0, a1, a2, a3, b0, b1);
            }
        }
        __syncthreads();
    }

    // epilogue: GRU update, write new h into vx slot0
#pragma unroll
    for (int nt = 0; nt < 8; nt++) {
        int gr0 = rowBase + wid * 16 + g4;
        int cv  = nt * 8 + 2 * t4;
        float bh0 = __ldg(&bh[cv]), bh1 = __ldg(&bh[cv + 1]);
#pragma unroll
        for (int half = 0; half < 2; half++) {
            int gr = gr0 + half * 8;
            float ht0 = tanhf(c[nt][half * 2 + 0] + bh0);
            float ht1 = tanhf(c[nt][half * 2 + 1] + bh1);
            float z0 = g_z[gr * HH + cv], z1 = g_z[gr * HH + cv + 1];
            float h0 = g_vh[gr * PART + cv], h1 = g_vh[gr * PART + cv + 1];
            g_vx[gr * PART + cv]     = z0 * h0 + (1.f - z0) * ht0;
            g_vx[gr * PART + cv + 1] = z1 * h1 + (1.f - z1) * ht1;
        }
    }
}

// ---------------- projection ----------------
__global__ void __launch_bounds__(256) k_proj(const float* __restrict__ pw,
                                              const float* __restrict__ pb,
                                              float* __restrict__ out) {
    __shared__ float Ws[64 * 32];
    __shared__ float Bsh[32];
    int tid = threadIdx.x;
    for (int i = tid; i < 64 * 32; i += 256) Ws[i] = pw[i];
    if (tid < 32) Bsh[tid] = pb[tid];
    __syncthreads();
    int w = tid >> 5, lane = tid & 31;
    int g = blockIdx.x * 8 + w;
    const float* x = g_vx + g * PART;
    float xv0 = x[lane], xv1 = x[32 + lane];
    float acc = Bsh[lane];
#pragma unroll
    for (int f = 0; f < 32; f++)
        acc += __shfl_sync(0xffffffffu, xv0, f) * Ws[f * 32 + lane];
#pragma unroll
    for (int f = 0; f < 32; f++)
        acc += __shfl_sync(0xffffffffu, xv1, f) * Ws[(32 + f) * 32 + lane];
    int n = g >> 3, b = g & 7;
    out[(b * NN + n) * 32 + lane] = acc;
}

// ---------------- launch ----------------
extern "C" void kernel_launch(void* const* d_in, const int* in_sizes, int n_in,
                              void* d_out, int out_size) {
    (void)in_sizes; (void)n_in; (void)out_size;
    const float* ew = (const float*)d_in[0];
    const float* hs = (const float*)d_in[1];
    const float* go = (const float*)d_in[2];
    const float* Wz = (const float*)d_in[3];
    const float* bz = (const float*)d_in[4];
    const float* Wr = (const float*)d_in[5];
    const float* br = (const float*)d_in[6];
    const float* Wh = (const float*)d_in[7];
    const float* bh = (const float*)d_in[8];
    const float* pw = (const float*)d_in[9];
    const float* pb = (const float*)d_in[10];
    const int*   ei = (const int*)d_in[11];
    float* out = (float*)d_out;

    k_zero  <<<(NN + 255) / 256, 256>>>();
    k_degcnt<<<(EE + 255) / 256, 256>>>(ew, ei);
    k_scan  <<<2, 1024>>>();
    k_fill  <<<(EE + 255) / 256, 256>>>(ew, ei);
    k_init_x<<<(NB * HH + 255) / 256, 256>>>(go);
    k_build_wzr<<<(2 * 640 * 128 + 255) / 256, 256>>>(Wz, Wr);
    k_build_wh <<<(2 * 640 * 64  + 255) / 256, 256>>>(Wh);

    dim3 g2(NN, 2, 2), g1(NN, 1, 2);
    for (int l = 0; l < 2; l++) {
        k_load_h<<<(NB * HH + 255) / 256, 256>>>(hs, l);

        k_prop2<<<g2, 128>>>(0, 1, 0, 1, 0, 2, 0, 0);   // slot1 = A_f s0; slot2 = A_r s0
        k_prop2<<<g2, 128>>>(0, 1, 1, 3, 2, 4, 1, 0);   // slot3/4 = 2 A(slot1/2) - s0

        k_gemm_zr<<<625, 256>>>(l, bz + l * HH, br + l * HH);

        k_prop2<<<g1, 128>>>(2, 2, 0, 1, 0, 2, 0, 0);
        k_prop2<<<g1, 128>>>(2, 2, 1, 3, 2, 4, 1, 0);

        k_gemm_h<<<625, 256>>>(l, bh + l * HH);          // -> new h in vx slot0
    }

    k_proj<<<NB / 8, 256>>>(pw, pb, out);
}

// round 6
// speedup vs baseline: 1.8957x; 1.2795x over previous
#include <cuda_runtime.h>
#include <cuda_fp16.h>

#define NN   10000
#define EE   160000
#define BB   8
#define HH   64
#define PART 320            // 5 slots * 64 features per (node,batch) row
#define NB   (NN*BB)        // 80000

// ---------------- device scratch ----------------
__device__ float g_deg_out[NN];
__device__ float g_deg_in[NN];
__device__ int   g_cnt[2][NN];
__device__ int   g_off[2][NN+1];
__device__ int   g_cur[2][NN];
__device__ int   g_nbr[2][EE];
__device__ float g_wgt[2][EE];

__device__ __half g_vx[NB*PART];   // x-part slots: 0=x 1=A_f x 2=A_r x 3=cheb_f 4=cheb_r
__device__ __half g_vh[NB*PART];   // h-part slots
__device__ __half g_vr[NB*PART];   // (R*h)-part slots
__device__ float  g_z [NB*HH];     // Z gate (fp32)
__device__ float  g_WZR[2*640*128];  // concat weights (tf32-rounded) for Z|R gemm
__device__ float  g_WH [2*640*64];   // concat weights (tf32-rounded) for H gemm

// ---------------- helpers ----------------
struct __align__(8)  h2x2 { __half2 a, b; };
struct __align__(16) h2x4 { __half2 a, b, c, d; };

__device__ __forceinline__ float sigm(float x) { return 1.f / (1.f + __expf(-x)); }

__device__ __forceinline__ float tf32r(float x) {
    unsigned u;
    asm("cvt.rna.tf32.f32 %0, %1;" : "=r"(u) : "f"(x));
    return __uint_as_float(u);
}

__device__ __forceinline__ void mma_tf32(float &c0, float &c1, float &c2, float &c3,
                                         unsigned a0, unsigned a1, unsigned a2, unsigned a3,
                                         unsigned b0, unsigned b1) {
    asm volatile(
        "mma.sync.aligned.m16n8k8.row.col.f32.tf32.tf32.f32 "
        "{%0,%1,%2,%3}, {%4,%5,%6,%7}, {%8,%9}, {%0,%1,%2,%3};"
        : "+f"(c0), "+f"(c1), "+f"(c2), "+f"(c3)
        : "r"(a0), "r"(a1), "r"(a2), "r"(a3), "r"(b0), "r"(b1));
}

__device__ __forceinline__ __half* partbuf(int id) {
    return id == 0 ? g_vx : (id == 1 ? g_vh : g_vr);
}

// ---------------- setup ----------------
__global__ void k_zero() {
    int i = blockIdx.x * 256 + threadIdx.x;
    if (i < NN) {
        g_deg_out[i] = 0.f; g_deg_in[i] = 0.f;
        g_cnt[0][i] = 0;    g_cnt[1][i] = 0;
    }
}

__global__ void k_degcnt(const float* __restrict__ ew, const int* __restrict__ ei) {
    int e = blockIdx.x * 256 + threadIdx.x;
    if (e >= EE) return;
    int s = ei[e], d = ei[EE + e];
    float w = ew[e];
    atomicAdd(&g_deg_out[s], w);
    atomicAdd(&g_deg_in[d],  w);
    atomicAdd(&g_cnt[0][d], 1);
    atomicAdd(&g_cnt[1][s], 1);
}

__global__ void k_scan() {   // grid=2, block=1024
    int d = blockIdx.x;
    __shared__ int sums[1024];
    int t = threadIdx.x;
    const int CH = 10;
    int base = t * CH;
    int s = 0;
    for (int i = 0; i < CH; i++) { int idx = base + i; if (idx < NN) s += g_cnt[d][idx]; }
    sums[t] = s; __syncthreads();
    for (int off = 1; off < 1024; off <<= 1) {
        int v = (t >= off) ? sums[t - off] : 0;
        __syncthreads();
        sums[t] += v;
        __syncthreads();
    }
    int run = (t == 0) ? 0 : sums[t - 1];
    for (int i = 0; i < CH; i++) {
        int idx = base + i;
        if (idx < NN) { g_off[d][idx] = run; g_cur[d][idx] = run; run += g_cnt[d][idx]; }
    }
    if (t == 1023) g_off[d][NN] = run;
}

__global__ void k_fill(const float* __restrict__ ew, const int* __restrict__ ei) {
    int e = blockIdx.x * 256 + threadIdx.x;
    if (e >= EE) return;
    int s = ei[e], d = ei[EE + e];
    float w = ew[e];
    float wo = g_deg_out[s]; float nout = w / (wo > 0.f ? wo : 1.f);
    float wi = g_deg_in[d];  float nin  = w / (wi > 0.f ? wi : 1.f);
    int p = atomicAdd(&g_cur[0][d], 1); g_nbr[0][p] = s; g_wgt[0][p] = nout;
    int q = atomicAdd(&g_cur[1][s], 1); g_nbr[1][q] = d; g_wgt[1][q] = nin;
}

__global__ void k_init_x(const float* __restrict__ go) {
    int t = blockIdx.x * 256 + threadIdx.x;
    if (t >= NB * HH) return;
    int f = t & 63; int rest = t >> 6;
    int n = rest % NN; int b = rest / NN;
    g_vx[(n * BB + b) * PART + f] = __float2half_rn(go[t]);
}

__global__ void k_load_h(const float* __restrict__ hs, int l) {
    int t = blockIdx.x * 256 + threadIdx.x;
    if (t >= NB * HH) return;
    int f = t & 63; int rest = t >> 6;
    int n = rest % NN; int b = rest / NN;
    g_vh[(n * BB + b) * PART + f] = __float2half_rn(hs[(size_t)l * NB * HH + t]);
}

// W layout [L,2,K,128,64]. Slots: 0:(dir0+dir1,k0) 1:(0,k1) 2:(1,k1) 3:(0,k2) 4:(1,k2)
__device__ __forceinline__ float wslot(const float* W, int l, int s, int wrow, int o) {
    if (s == 0) {
        return W[((((l*2+0)*3+0)*128 + wrow)*64) + o] +
               W[((((l*2+1)*3+0)*128 + wrow)*64) + o];
    }
    int dir = (s == 1 || s == 3) ? 0 : 1;
    int k   = (s <= 2) ? 1 : 2;
    return W[((((l*2+dir)*3+k)*128 + wrow)*64) + o];
}

__global__ void k_build_wzr(const float* __restrict__ Wz, const float* __restrict__ Wr) {
    int idx = blockIdx.x * 256 + threadIdx.x;
    if (idx >= 2 * 640 * 128) return;
    int l = idx >= 640 * 128 ? 1 : 0;
    int li = idx - l * 640 * 128;
    int j = li >> 7, c = li & 127;
    int p = j / 320, s = (j % 320) / 64, f = j & 63;
    int wrow = p * 64 + f;
    const float* W = (c < 64) ? Wz : Wr;
    g_WZR[l * 640 * 128 + j * 128 + c] = tf32r(wslot(W, l, s, wrow, c & 63));
}

__global__ void k_build_wh(const float* __restrict__ Wh) {
    int idx = blockIdx.x * 256 + threadIdx.x;
    if (idx >= 2 * 640 * 64) return;
    int l = idx >= 640 * 64 ? 1 : 0;
    int li = idx - l * 640 * 64;
    int j = li >> 6, o = li & 63;
    int p = j / 320, s = (j % 320) / 64, f = j & 63;
    g_WH[l * 640 * 64 + j * 64 + o] = tf32r(wslot(Wh, l, s, p * 64 + f, o));
}

// ---------------- propagation (fp16 storage, fp32 accumulate) ----------------
// grid: (NN, nbuf, 2 dirs); block 128: warp = 2 batches, 16 lanes * 4 halves = 64 feats
__global__ void __launch_bounds__(128) k_prop2(int bufA, int bufB,
                                               int s_in_f, int s_out_f,
                                               int s_in_r, int s_out_r,
                                               int cheb, int s_prev) {
    int dir = blockIdx.z;
    __half* buf = partbuf(blockIdx.y == 0 ? bufA : bufB);
    const int*   off = g_off[dir];
    const int*   nbr = g_nbr[dir];
    const float* wgt = g_wgt[dir];
    int s_in  = dir ? s_in_r  : s_in_f;
    int s_out = dir ? s_out_r : s_out_f;
    int n    = blockIdx.x;
    int w    = threadIdx.x >> 5;
    int lane = threadIdx.x & 31;
    int b    = w * 2 + (lane >> 4);
    int fo   = (lane & 15) * 4;        // half offset within 64
    int beg = off[n], end = off[n + 1];
    int inoff = s_in * 64 + fo;
    float4 acc = make_float4(0.f, 0.f, 0.f, 0.f);
    int j = beg;
    int e8 = beg + ((end - beg) & ~7);
    for (; j < e8; j += 8) {
#pragma unroll
        for (int u = 0; u < 8; u++) {
            int   m = __ldg(&nbr[j + u]);
            float ww = __ldg(&wgt[j + u]);
            h2x2 v = *(const h2x2*)(buf + (m * BB + b) * PART + inoff);
            float2 f01 = __half22float2(v.a);
            float2 f23 = __half22float2(v.b);
            acc.x += ww * f01.x; acc.y += ww * f01.y;
            acc.z += ww * f23.x; acc.w += ww * f23.y;
        }
    }
    for (; j < end; j++) {
        int   m = __ldg(&nbr[j]);
        float ww = __ldg(&wgt[j]);
        h2x2 v = *(const h2x2*)(buf + (m * BB + b) * PART + inoff);
        float2 f01 = __half22float2(v.a);
        float2 f23 = __half22float2(v.b);
        acc.x += ww * f01.x; acc.y += ww * f01.y;
        acc.z += ww * f23.x; acc.w += ww * f23.y;
    }
    int orow = (n * BB + b) * PART;
    float4 res = acc;
    if (cheb) {
        h2x2 pv = *(const h2x2*)(buf + orow + s_prev * 64 + fo);
        float2 p01 = __half22float2(pv.a);
        float2 p23 = __half22float2(pv.b);
        res.x = 2.f * acc.x - p01.x; res.y = 2.f * acc.y - p01.y;
        res.z = 2.f * acc.z - p23.x; res.w = 2.f * acc.w - p23.y;
    }
    h2x2 o;
    o.a = __floats2half2_rn(res.x, res.y);
    o.b = __floats2half2_rn(res.z, res.w);
    *(h2x2*)(buf + orow + s_out * 64 + fo) = o;
}

// ---------------- tf32 tensor-core GEMMs ----------------
// Z|R: [80000 x 640] @ [640 x 128]; A row = (vx row | vh row), fp16 in gmem
// Block 256 = 8 warps, tile 128x128, warps 4x2 (32 rows x 64 cols each)
__global__ void __launch_bounds__(256) k_gemm_zr(int l,
                                                 const float* __restrict__ bz,
                                                 const float* __restrict__ br) {
    __shared__ float As[128][36];   // fp16->fp32 (tf32-exact)
    __shared__ float Bs[32][136];   // k-major B (pre-rounded tf32)
    const float* W = g_WZR + l * 640 * 128;
    int tid = threadIdx.x;
    int wid = tid >> 5, lane = tid & 31;
    int warpM = wid & 3, warpN = wid >> 2;
    int g4 = lane >> 2, t4 = lane & 3;
    int rowBase = blockIdx.x * 128;

    float c[2][8][4];
#pragma unroll
    for (int mt = 0; mt < 2; mt++)
#pragma unroll
        for (int nt = 0; nt < 8; nt++)
#pragma unroll
            for (int i = 0; i < 4; i++) c[mt][nt][i] = 0.f;

    for (int kk = 0; kk < 20; kk++) {
        const __half* Asrc = (kk < 10) ? g_vx : g_vh;
        int soff = (kk < 10 ? kk : kk - 10) * 32;
#pragma unroll
        for (int t = 0; t < 2; t++) {           // A: 128x32 halves = 512 h2x4
            int id = tid + t * 256;
            int r = id >> 2, c8 = (id & 3) * 8;
            h2x4 v = *(const h2x4*)(Asrc + (rowBase + r) * PART + soff + c8);
            float2 f;
            f = __half22float2(v.a); As[r][c8 + 0] = f.x; As[r][c8 + 1] = f.y;
            f = __half22float2(v.b); As[r][c8 + 2] = f.x; As[r][c8 + 3] = f.y;
            f = __half22float2(v.c); As[r][c8 + 4] = f.x; As[r][c8 + 5] = f.y;
            f = __half22float2(v.d); As[r][c8 + 6] = f.x; As[r][c8 + 7] = f.y;
        }
#pragma unroll
        for (int t = 0; t < 4; t++) {           // B: 32x128 = 1024 float4
            int id = tid + t * 256;
            int kr = id >> 5, c4 = id & 31;
            float4 v = *(const float4*)(W + (kk * 32 + kr) * 128 + c4 * 4);
            int cb = c4 * 4;
            Bs[kr][cb + 0] = v.x; Bs[kr][cb + 1] = v.y;
            Bs[kr][cb + 2] = v.z; Bs[kr][cb + 3] = v.w;
        }
        __syncthreads();
#pragma unroll
        for (int kc = 0; kc < 4; kc++) {
            int k0 = kc * 8;
            unsigned a[2][4];
#pragma unroll
            for (int mt = 0; mt < 2; mt++) {
                int rm = warpM * 32 + mt * 16;
                a[mt][0] = __float_as_uint(As[rm + g4][k0 + t4]);
                a[mt][1] = __float_as_uint(As[rm + g4 + 8][k0 + t4]);
                a[mt][2] = __float_as_uint(As[rm + g4][k0 + t4 + 4]);
                a[mt][3] = __float_as_uint(As[rm + g4 + 8][k0 + t4 + 4]);
            }
#pragma unroll
            for (int nt = 0; nt < 8; nt++) {
                int cn = warpN * 64 + nt * 8;
                unsigned b0 = __float_as_uint(Bs[k0 + t4][cn + g4]);
                unsigned b1 = __float_as_uint(Bs[k0 + t4 + 4][cn + g4]);
#pragma unroll
                for (int mt = 0; mt < 2; mt++)
                    mma_tf32(c[mt][nt][0], c[mt][nt][1], c[mt][nt][2], c[mt][nt][3],
                             a[mt][0], a[mt][1], a[mt][2], a[mt][3], b0, b1);
            }
        }
        __syncthreads();
    }

    // epilogue: warpN==0 -> Z gate; warpN==1 -> R gate * h
#pragma unroll
    for (int mt = 0; mt < 2; mt++) {
#pragma unroll
        for (int nt = 0; nt < 8; nt++) {
            int gr0 = rowBase + warpM * 32 + mt * 16 + g4;
            int cv  = nt * 8 + 2 * t4;
            if (warpN == 0) {
                float bz0 = __ldg(&bz[cv]), bz1 = __ldg(&bz[cv + 1]);
                g_z[gr0 * HH + cv]           = sigm(c[mt][nt][0] + bz0);
                g_z[gr0 * HH + cv + 1]       = sigm(c[mt][nt][1] + bz1);
                g_z[(gr0 + 8) * HH + cv]     = sigm(c[mt][nt][2] + bz0);
                g_z[(gr0 + 8) * HH + cv + 1] = sigm(c[mt][nt][3] + bz1);
            } else {
                float br0 = __ldg(&br[cv]), br1 = __ldg(&br[cv + 1]);
                float h00 = __half2float(g_vh[gr0 * PART + cv]);
                float h01 = __half2float(g_vh[gr0 * PART + cv + 1]);
                float h10 = __half2float(g_vh[(gr0 + 8) * PART + cv]);
                float h11 = __half2float(g_vh[(gr0 + 8) * PART + cv + 1]);
                g_vr[gr0 * PART + cv]           = __float2half_rn(sigm(c[mt][nt][0] + br0) * h00);
                g_vr[gr0 * PART + cv + 1]       = __float2half_rn(sigm(c[mt][nt][1] + br1) * h01);
                g_vr[(gr0 + 8) * PART + cv]     = __float2half_rn(sigm(c[mt][nt][2] + br0) * h10);
                g_vr[(gr0 + 8) * PART + cv + 1] = __float2half_rn(sigm(c[mt][nt][3] + br1) * h11);
            }
        }
    }
}

// H: [80000 x 640] @ [640 x 64]; A row = (vx row | vr row). GRU update -> vx slot0
// Block 256 = 8 warps, tile 128x64, each warp 16 rows x 64 cols
__global__ void __launch_bounds__(256) k_gemm_h(int l, const float* __restrict__ bh) {
    __shared__ float As[128][36];
    __shared__ float Bs[32][72];
    const float* W = g_WH + l * 640 * 64;
    int tid = threadIdx.x;
    int wid = tid >> 5, lane = tid & 31;
    int g4 = lane >> 2, t4 = lane & 3;
    int rowBase = blockIdx.x * 128;

    float c[8][4];
#pragma unroll
    for (int nt = 0; nt < 8; nt++)
#pragma unroll
        for (int i = 0; i < 4; i++) c[nt][i] = 0.f;

    for (int kk = 0; kk < 20; kk++) {
        const __half* Asrc = (kk < 10) ? g_vx : g_vr;
        int soff = (kk < 10 ? kk : kk - 10) * 32;
#pragma unroll
        for (int t = 0; t < 2; t++) {           // A: 512 h2x4
            int id = tid + t * 256;
            int r = id >> 2, c8 = (id & 3) * 8;
            h2x4 v = *(const h2x4*)(Asrc + (rowBase + r) * PART + soff + c8);
            float2 f;
            f = __half22float2(v.a); As[r][c8 + 0] = f.x; As[r][c8 + 1] = f.y;
            f = __half22float2(v.b); As[r][c8 + 2] = f.x; As[r][c8 + 3] = f.y;
            f = __half22float2(v.c); As[r][c8 + 4] = f.x; As[r][c8 + 5] = f.y;
            f = __half22float2(v.d); As[r][c8 + 6] = f.x; As[r][c8 + 7] = f.y;
        }
#pragma unroll
        for (int t = 0; t < 2; t++) {           // B: 32x64 = 512 float4
            int id = tid + t * 256;
            int kr = id >> 4, c4 = id & 15;
            float4 v = *(const float4*)(W + (kk * 32 + kr) * 64 + c4 * 4);
            int cb = c4 * 4;
            Bs[kr][cb + 0] = v.x; Bs[kr][cb + 1] = v.y;
            Bs[kr][cb + 2] = v.z; Bs[kr][cb + 3] = v.w;
        }
        __syncthreads();
#pragma unroll
        for (int kc = 0; kc < 4; kc++) {
            int k0 = kc * 8;
            int rm = wid * 16;
            unsigned a0 = __float_as_uint(As[rm + g4][k0 + t4]);
            unsigned a1 = __float_as_uint(As[rm + g4 + 8][k0 + t4]);
            unsigned a2 = __float_as_uint(As[rm + g4][k0 + t4 + 4]);
            unsigned a3 = __float_as_uint(As[rm + g4 + 8][k0 + t4 + 4]);
#pragma unroll
            for (int nt = 0; nt < 8; nt++) {
                int cn = nt * 8;
                unsigned b0 = __float_as_uint(Bs[k0 + t4][cn + g4]);
                unsigned b1 = __float_as_uint(Bs[k0 + t4 + 4][cn + g4]);
                mma_tf32(c[nt][0], c[nt][1], c[nt][2], c[nt][3], a0, a1, a2, a3, b0, b1);
            }
        }
        __syncthreads();
    }

    // epilogue: GRU update, write new h into vx slot0 (fp16)
#pragma unroll
    for (int nt = 0; nt < 8; nt++) {
        int gr0 = rowBase + wid * 16 + g4;
        int cv  = nt * 8 + 2 * t4;
        float bh0 = __ldg(&bh[cv]), bh1 = __ldg(&bh[cv + 1]);
#pragma unroll
        for (int half_i = 0; half_i < 2; half_i++) {
            int gr = gr0 + half_i * 8;
            float ht0 = tanhf(c[nt][half_i * 2 + 0] + bh0);
            float ht1 = tanhf(c[nt][half_i * 2 + 1] + bh1);
            float z0 = g_z[gr * HH + cv], z1 = g_z[gr * HH + cv + 1];
            float h0 = __half2float(g_vh[gr * PART + cv]);
            float h1 = __half2float(g_vh[gr * PART + cv + 1]);
            g_vx[gr * PART + cv]     = __float2half_rn(z0 * h0 + (1.f - z0) * ht0);
            g_vx[gr * PART + cv + 1] = __float2half_rn(z1 * h1 + (1.f - z1) * ht1);
        }
    }
}

// ---------------- projection ----------------
__global__ void __launch_bounds__(256) k_proj(const float* __restrict__ pw,
                                              const float* __restrict__ pb,
                                              float* __restrict__ out) {
    __shared__ float Ws[64 * 32];
    __shared__ float Bsh[32];
    int tid = threadIdx.x;
    for (int i = tid; i < 64 * 32; i += 256) Ws[i] = pw[i];
    if (tid < 32) Bsh[tid] = pb[tid];
    __syncthreads();
    int w = tid >> 5, lane = tid & 31;
    int g = blockIdx.x * 8 + w;
    const __half* x = g_vx + g * PART;
    float xv0 = __half2float(x[lane]);
    float xv1 = __half2float(x[32 + lane]);
    float acc = Bsh[lane];
#pragma unroll
    for (int f = 0; f < 32; f++)
        acc += __shfl_sync(0xffffffffu, xv0, f) * Ws[f * 32 + lane];
#pragma unroll
    for (int f = 0; f < 32; f++)
        acc += __shfl_sync(0xffffffffu, xv1, f) * Ws[(32 + f) * 32 + lane];
    int n = g >> 3, b = g & 7;
    out[(b * NN + n) * 32 + lane] = acc;
}

// ---------------- launch ----------------
extern "C" void kernel_launch(void* const* d_in, const int* in_sizes, int n_in,
                              void* d_out, int out_size) {
    (void)in_sizes; (void)n_in; (void)out_size;
    const float* ew = (const float*)d_in[0];
    const float* hs = (const float*)d_in[1];
    const float* go = (const float*)d_in[2];
    const float* Wz = (const float*)d_in[3];
    const float* bz = (const float*)d_in[4];
    const float* Wr = (const float*)d_in[5];
    const float* br = (const float*)d_in[6];
    const float* Wh = (const float*)d_in[7];
    const float* bh = (const float*)d_in[8];
    const float* pw = (const float*)d_in[9];
    const float* pb = (const float*)d_in[10];
    const int*   ei = (const int*)d_in[11];
    float* out = (float*)d_out;

    k_zero  <<<(NN + 255) / 256, 256>>>();
    k_degcnt<<<(EE + 255) / 256, 256>>>(ew, ei);
    k_scan  <<<2, 1024>>>();
    k_fill  <<<(EE + 255) / 256, 256>>>(ew, ei);
    k_init_x<<<(NB * HH + 255) / 256, 256>>>(go);
    k_build_wzr<<<(2 * 640 * 128 + 255) / 256, 256>>>(Wz, Wr);
    k_build_wh <<<(2 * 640 * 64  + 255) / 256, 256>>>(Wh);

    dim3 g2(NN, 2, 2), g1(NN, 1, 2);
    for (int l = 0; l < 2; l++) {
        k_load_h<<<(NB * HH + 255) / 256, 256>>>(hs, l);

        k_prop2<<<g2, 128>>>(0, 1, 0, 1, 0, 2, 0, 0);   // slot1 = A_f s0; slot2 = A_r s0
        k_prop2<<<g2, 128>>>(0, 1, 1, 3, 2, 4, 1, 0);   // slot3/4 = 2 A(slot1/2) - s0

        k_gemm_zr<<<625, 256>>>(l, bz + l * HH, br + l * HH);

        k_prop2<<<g1, 128>>>(2, 2, 0, 1, 0, 2, 0, 0);
        k_prop2<<<g1, 128>>>(2, 2, 1, 3, 2, 4, 1, 0);

        k_gemm_h<<<625, 256>>>(l, bh + l * HH);          // -> new h in vx slot0
    }

    k_proj<<<NB / 8, 256>>>(pw, pb, out);
}

// round 7
// speedup vs baseline: 1.9124x; 1.0088x over previous
#include <cuda_runtime.h>
#include <cuda_fp16.h>

#define NN   10000
#define EE   160000
#define BB   8
#define HH   64
#define PART 320            // 5 slots * 64 features per (node,batch) row
#define NB   (NN*BB)        // 80000
#define VHL  (NB*PART)      // one vh layer

// ---------------- device scratch ----------------
__device__ float g_deg_out[NN];
__device__ float g_deg_in[NN];
__device__ int   g_cnt[2][NN];
__device__ int   g_off[2][NN+1];
__device__ int   g_cur[2][NN];
__device__ int   g_nbr[2][EE];
__device__ float g_wgt[2][EE];

__device__ __half g_vx[VHL];      // x-part slots: 0=x 1=A_f x 2=A_r x 3=cheb_f 4=cheb_r
__device__ __half g_vh[2*VHL];    // h-part slots, per layer
__device__ __half g_vr[VHL];      // (R*h)-part slots
__device__ float  g_z [NB*HH];    // Z gate (fp32)
__device__ __half g_WZR[2*128*640];  // fp16 weights, n-major [l][n][640] for Z|R gemm
__device__ __half g_WH [2*64*640];   // fp16 weights, n-major [l][n][640] for H gemm

// ---------------- helpers ----------------
struct __align__(8)  h2x2 { __half2 a, b; };
struct __align__(16) h2x4 { __half2 a, b, c, d; };

__device__ __forceinline__ float sigm(float x) { return 1.f / (1.f + __expf(-x)); }

__device__ __forceinline__ void mma_f16(float &c0, float &c1, float &c2, float &c3,
                                        unsigned a0, unsigned a1, unsigned a2, unsigned a3,
                                        unsigned b0, unsigned b1) {
    asm volatile(
        "mma.sync.aligned.m16n8k16.row.col.f32.f16.f16.f32 "
        "{%0,%1,%2,%3}, {%4,%5,%6,%7}, {%8,%9}, {%0,%1,%2,%3};"
        : "+f"(c0), "+f"(c1), "+f"(c2), "+f"(c3)
        : "r"(a0), "r"(a1), "r"(a2), "r"(a3), "r"(b0), "r"(b1));
}

__device__ __forceinline__ __half* partbuf(int id, int l) {
    return id == 0 ? g_vx : (id == 1 ? g_vh + l * VHL : g_vr);
}

// ---------------- setup ----------------
__global__ void k_zero() {
    int i = blockIdx.x * 256 + threadIdx.x;
    if (i < NN) {
        g_deg_out[i] = 0.f; g_deg_in[i] = 0.f;
        g_cnt[0][i] = 0;    g_cnt[1][i] = 0;
    }
}

__global__ void k_degcnt(const float* __restrict__ ew, const int* __restrict__ ei) {
    int e = blockIdx.x * 256 + threadIdx.x;
    if (e >= EE) return;
    int s = ei[e], d = ei[EE + e];
    float w = ew[e];
    atomicAdd(&g_deg_out[s], w);
    atomicAdd(&g_deg_in[d],  w);
    atomicAdd(&g_cnt[0][d], 1);
    atomicAdd(&g_cnt[1][s], 1);
}

__global__ void k_scan() {   // grid=2, block=1024
    int d = blockIdx.x;
    __shared__ int sums[1024];
    int t = threadIdx.x;
    const int CH = 10;
    int base = t * CH;
    int s = 0;
    for (int i = 0; i < CH; i++) { int idx = base + i; if (idx < NN) s += g_cnt[d][idx]; }
    sums[t] = s; __syncthreads();
    for (int off = 1; off < 1024; off <<= 1) {
        int v = (t >= off) ? sums[t - off] : 0;
        __syncthreads();
        sums[t] += v;
        __syncthreads();
    }
    int run = (t == 0) ? 0 : sums[t - 1];
    for (int i = 0; i < CH; i++) {
        int idx = base + i;
        if (idx < NN) { g_off[d][idx] = run; g_cur[d][idx] = run; run += g_cnt[d][idx]; }
    }
    if (t == 1023) g_off[d][NN] = run;
}

__global__ void k_fill(const float* __restrict__ ew, const int* __restrict__ ei) {
    int e = blockIdx.x * 256 + threadIdx.x;
    if (e >= EE) return;
    int s = ei[e], d = ei[EE + e];
    float w = ew[e];
    float wo = g_deg_out[s]; float nout = w / (wo > 0.f ? wo : 1.f);
    float wi = g_deg_in[d];  float nin  = w / (wi > 0.f ? wi : 1.f);
    int p = atomicAdd(&g_cur[0][d], 1); g_nbr[0][p] = s; g_wgt[0][p] = nout;
    int q = atomicAdd(&g_cur[1][s], 1); g_nbr[1][q] = d; g_wgt[1][q] = nin;
}

__global__ void k_init_x(const float* __restrict__ go) {
    int t = blockIdx.x * 256 + threadIdx.x;
    if (t >= NB * HH) return;
    int f = t & 63; int rest = t >> 6;
    int n = rest % NN; int b = rest / NN;
    g_vx[(n * BB + b) * PART + f] = __float2half_rn(go[t]);
}

__global__ void k_load_h(const float* __restrict__ hs) {   // both layers
    int t = blockIdx.x * 256 + threadIdx.x;
    if (t >= 2 * NB * HH) return;
    int l = t >= NB * HH ? 1 : 0;
    int tt = t - l * NB * HH;
    int f = tt & 63; int rest = tt >> 6;
    int n = rest % NN; int b = rest / NN;
    g_vh[l * VHL + (n * BB + b) * PART + f] = __float2half_rn(hs[t]);
}

// W layout [L,2,K,128,64]. Slots: 0:(dir0+dir1,k0) 1:(0,k1) 2:(1,k1) 3:(0,k2) 4:(1,k2)
__device__ __forceinline__ float wslot(const float* W, int l, int s, int wrow, int o) {
    if (s == 0) {
        return W[((((l*2+0)*3+0)*128 + wrow)*64) + o] +
               W[((((l*2+1)*3+0)*128 + wrow)*64) + o];
    }
    int dir = (s == 1 || s == 3) ? 0 : 1;
    int k   = (s <= 2) ? 1 : 2;
    return W[((((l*2+dir)*3+k)*128 + wrow)*64) + o];
}

// builds fp16 n-major: g_WZR[l][n][j], j in [0,640)
__global__ void k_build_wzr(const float* __restrict__ Wz, const float* __restrict__ Wr) {
    int idx = blockIdx.x * 256 + threadIdx.x;
    if (idx >= 2 * 128 * 640) return;
    int l = idx >= 128 * 640 ? 1 : 0;
    int li = idx - l * 128 * 640;
    int n = li / 640, j = li % 640;
    int p = j / 320, s = (j % 320) / 64, f = j & 63;
    int wrow = p * 64 + f;
    const float* W = (n < 64) ? Wz : Wr;
    g_WZR[l * 128 * 640 + n * 640 + j] = __float2half_rn(wslot(W, l, s, wrow, n & 63));
}

__global__ void k_build_wh(const float* __restrict__ Wh) {
    int idx = blockIdx.x * 256 + threadIdx.x;
    if (idx >= 2 * 64 * 640) return;
    int l = idx >= 64 * 640 ? 1 : 0;
    int li = idx - l * 64 * 640;
    int n = li / 640, j = li % 640;
    int p = j / 320, s = (j % 320) / 64, f = j & 63;
    g_WH[l * 64 * 640 + n * 640 + j] = __float2half_rn(wslot(Wh, l, s, p * 64 + f, n));
}

// ---------------- propagation (fp16 storage, fp32 accumulate) ----------------
// grid: (NN, nbuf, 2 dirs); block 128: warp = 2 batches, 16 lanes * 4 halves = 64 feats
__global__ void __launch_bounds__(128) k_prop2(int bufA, int bufB, int lvh,
                                               int s_in_f, int s_out_f,
                                               int s_in_r, int s_out_r,
                                               int cheb, int s_prev) {
    int dir = blockIdx.z;
    __half* buf = partbuf(blockIdx.y == 0 ? bufA : bufB, lvh);
    const int*   off = g_off[dir];
    const int*   nbr = g_nbr[dir];
    const float* wgt = g_wgt[dir];
    int s_in  = dir ? s_in_r  : s_in_f;
    int s_out = dir ? s_out_r : s_out_f;
    int n    = blockIdx.x;
    int w    = threadIdx.x >> 5;
    int lane = threadIdx.x & 31;
    int b    = w * 2 + (lane >> 4);
    int fo   = (lane & 15) * 4;
    int beg = off[n], end = off[n + 1];
    int inoff = s_in * 64 + fo;
    float4 acc = make_float4(0.f, 0.f, 0.f, 0.f);
    int j = beg;
    int e8 = beg + ((end - beg) & ~7);
    for (; j < e8; j += 8) {
#pragma unroll
        for (int u = 0; u < 8; u++) {
            int   m = __ldg(&nbr[j + u]);
            float ww = __ldg(&wgt[j + u]);
            h2x2 v = *(const h2x2*)(buf + (m * BB + b) * PART + inoff);
            float2 f01 = __half22float2(v.a);
            float2 f23 = __half22float2(v.b);
            acc.x += ww * f01.x; acc.y += ww * f01.y;
            acc.z += ww * f23.x; acc.w += ww * f23.y;
        }
    }
    for (; j < end; j++) {
        int   m = __ldg(&nbr[j]);
        float ww = __ldg(&wgt[j]);
        h2x2 v = *(const h2x2*)(buf + (m * BB + b) * PART + inoff);
        float2 f01 = __half22float2(v.a);
        float2 f23 = __half22float2(v.b);
        acc.x += ww * f01.x; acc.y += ww * f01.y;
        acc.z += ww * f23.x; acc.w += ww * f23.y;
    }
    int orow = (n * BB + b) * PART;
    float4 res = acc;
    if (cheb) {
        h2x2 pv = *(const h2x2*)(buf + orow + s_prev * 64 + fo);
        float2 p01 = __half22float2(pv.a);
        float2 p23 = __half22float2(pv.b);
        res.x = 2.f * acc.x - p01.x; res.y = 2.f * acc.y - p01.y;
        res.z = 2.f * acc.z - p23.x; res.w = 2.f * acc.w - p23.y;
    }
    h2x2 o;
    o.a = __floats2half2_rn(res.x, res.y);
    o.b = __floats2half2_rn(res.z, res.w);
    *(h2x2*)(buf + orow + s_out * 64 + fo) = o;
}

// ---------------- fp16 tensor-core GEMMs ----------------
// Z|R: [80000 x 640] @ [640 x 128]; A row = (vx row | vh row), all fp16
// Block 256 = 8 warps, tile 128x128, warps 4x2 (32 rows x 64 cols each)
__global__ void __launch_bounds__(256) k_gemm_zr(int l,
                                                 const float* __restrict__ bz,
                                                 const float* __restrict__ br) {
    __shared__ __half As[128][40];   // row-major, padded (conflict-free quad reads)
    __shared__ __half Bs[128][40];   // n-major: Bs[n][k]
    const __half* W = g_WZR + l * 128 * 640;
    const __half* vh = g_vh + l * VHL;
    int tid = threadIdx.x;
    int wid = tid >> 5, lane = tid & 31;
    int warpM = wid & 3, warpN = wid >> 2;
    int g4 = lane >> 2, t4 = lane & 3;
    int rowBase = blockIdx.x * 128;

    float c[2][8][4];
#pragma unroll
    for (int mt = 0; mt < 2; mt++)
#pragma unroll
        for (int nt = 0; nt < 8; nt++)
#pragma unroll
            for (int i = 0; i < 4; i++) c[mt][nt][i] = 0.f;

    for (int kk = 0; kk < 20; kk++) {
        const __half* Asrc = (kk < 10) ? g_vx : vh;
        int soff = (kk < 10 ? kk : kk - 10) * 32;
#pragma unroll
        for (int t = 0; t < 2; t++) {           // A: 128x32 halves = 512 h2x4
            int id = tid + t * 256;
            int r = id >> 2, c8 = (id & 3) * 8;
            *(h2x4*)&As[r][c8] = *(const h2x4*)(Asrc + (rowBase + r) * PART + soff + c8);
        }
#pragma unroll
        for (int t = 0; t < 2; t++) {           // B: 128 n x 32 k halves = 512 h2x4
            int id = tid + t * 256;
            int n = id >> 2, c8 = (id & 3) * 8;
            *(h2x4*)&Bs[n][c8] = *(const h2x4*)(W + n * 640 + kk * 32 + c8);
        }
        __syncthreads();
#pragma unroll
        for (int kc = 0; kc < 2; kc++) {
            int k0 = kc * 16;
            int kA = k0 + 2 * t4;
            unsigned a[2][4];
#pragma unroll
            for (int mt = 0; mt < 2; mt++) {
                int rm = warpM * 32 + mt * 16;
                a[mt][0] = *(const unsigned*)&As[rm + g4][kA];
                a[mt][1] = *(const unsigned*)&As[rm + g4 + 8][kA];
                a[mt][2] = *(const unsigned*)&As[rm + g4][kA + 8];
                a[mt][3] = *(const unsigned*)&As[rm + g4 + 8][kA + 8];
            }
#pragma unroll
            for (int nt = 0; nt < 8; nt++) {
                int cn = warpN * 64 + nt * 8;
                unsigned b0 = *(const unsigned*)&Bs[cn + g4][kA];
                unsigned b1 = *(const unsigned*)&Bs[cn + g4][kA + 8];
#pragma unroll
                for (int mt = 0; mt < 2; mt++)
                    mma_f16(c[mt][nt][0], c[mt][nt][1], c[mt][nt][2], c[mt][nt][3],
                            a[mt][0], a[mt][1], a[mt][2], a[mt][3], b0, b1);
            }
        }
        __syncthreads();
    }

    // epilogue: warpN==0 -> Z gate; warpN==1 -> R gate * h
#pragma unroll
    for (int mt = 0; mt < 2; mt++) {
#pragma unroll
        for (int nt = 0; nt < 8; nt++) {
            int gr0 = rowBase + warpM * 32 + mt * 16 + g4;
            int cv  = nt * 8 + 2 * t4;
            if (warpN == 0) {
                float bz0 = __ldg(&bz[cv]), bz1 = __ldg(&bz[cv + 1]);
                g_z[gr0 * HH + cv]           = sigm(c[mt][nt][0] + bz0);
                g_z[gr0 * HH + cv + 1]       = sigm(c[mt][nt][1] + bz1);
                g_z[(gr0 + 8) * HH + cv]     = sigm(c[mt][nt][2] + bz0);
                g_z[(gr0 + 8) * HH + cv + 1] = sigm(c[mt][nt][3] + bz1);
            } else {
                float br0 = __ldg(&br[cv]), br1 = __ldg(&br[cv + 1]);
                float h00 = __half2float(vh[gr0 * PART + cv]);
                float h01 = __half2float(vh[gr0 * PART + cv + 1]);
                float h10 = __half2float(vh[(gr0 + 8) * PART + cv]);
                float h11 = __half2float(vh[(gr0 + 8) * PART + cv + 1]);
                g_vr[gr0 * PART + cv]           = __float2half_rn(sigm(c[mt][nt][0] + br0) * h00);
                g_vr[gr0 * PART + cv + 1]       = __float2half_rn(sigm(c[mt][nt][1] + br1) * h01);
                g_vr[(gr0 + 8) * PART + cv]     = __float2half_rn(sigm(c[mt][nt][2] + br0) * h10);
                g_vr[(gr0 + 8) * PART + cv + 1] = __float2half_rn(sigm(c[mt][nt][3] + br1) * h11);
            }
        }
    }
}

// H: [80000 x 640] @ [640 x 64]; A row = (vx row | vr row). GRU update -> vx slot0
// Block 256 = 8 warps, tile 128x64, each warp 16 rows x 64 cols
__global__ void __launch_bounds__(256) k_gemm_h(int l, const float* __restrict__ bh) {
    __shared__ __half As[128][40];
    __shared__ __half Bs[64][40];
    const __half* W = g_WH + l * 64 * 640;
    const __half* vh = g_vh + l * VHL;
    int tid = threadIdx.x;
    int wid = tid >> 5, lane = tid & 31;
    int g4 = lane >> 2, t4 = lane & 3;
    int rowBase = blockIdx.x * 128;

    float c[8][4];
#pragma unroll
    for (int nt = 0; nt < 8; nt++)
#pragma unroll
        for (int i = 0; i < 4; i++) c[nt][i] = 0.f;

    for (int kk = 0; kk < 20; kk++) {
        const __half* Asrc = (kk < 10) ? g_vx : g_vr;
        int soff = (kk < 10 ? kk : kk - 10) * 32;
#pragma unroll
        for (int t = 0; t < 2; t++) {           // A: 512 h2x4
            int id = tid + t * 256;
            int r = id >> 2, c8 = (id & 3) * 8;
            *(h2x4*)&As[r][c8] = *(const h2x4*)(Asrc + (rowBase + r) * PART + soff + c8);
        }
        {                                       // B: 64 n x 32 k = 256 h2x4
            int n = tid >> 2, c8 = (tid & 3) * 8;
            *(h2x4*)&Bs[n][c8] = *(const h2x4*)(W + n * 640 + kk * 32 + c8);
        }
        __syncthreads();
#pragma unroll
        for (int kc = 0; kc < 2; kc++) {
            int kA = kc * 16 + 2 * t4;
            int rm = wid * 16;
            unsigned a0 = *(const unsigned*)&As[rm + g4][kA];
            unsigned a1 = *(const unsigned*)&As[rm + g4 + 8][kA];
            unsigned a2 = *(const unsigned*)&As[rm + g4][kA + 8];
            unsigned a3 = *(const unsigned*)&As[rm + g4 + 8][kA + 8];
#pragma unroll
            for (int nt = 0; nt < 8; nt++) {
                unsigned b0 = *(const unsigned*)&Bs[nt * 8 + g4][kA];
                unsigned b1 = *(const unsigned*)&Bs[nt * 8 + g4][kA + 8];
                mma_f16(c[nt][0], c[nt][1], c[nt][2], c[nt][3], a0, a1, a2, a3, b0, b1);
            }
        }
        __syncthreads();
    }

    // epilogue: GRU update, write new h into vx slot0 (fp16)
#pragma unroll
    for (int nt = 0; nt < 8; nt++) {
        int gr0 = rowBase + wid * 16 + g4;
        int cv  = nt * 8 + 2 * t4;
        float bh0 = __ldg(&bh[cv]), bh1 = __ldg(&bh[cv + 1]);
#pragma unroll
        for (int half_i = 0; half_i < 2; half_i++) {
            int gr = gr0 + half_i * 8;
            float ht0 = tanhf(c[nt][half_i * 2 + 0] + bh0);
            float ht1 = tanhf(c[nt][half_i * 2 + 1] + bh1);
            float z0 = g_z[gr * HH + cv], z1 = g_z[gr * HH + cv + 1];
            float h0 = __half2float(vh[gr * PART + cv]);
            float h1 = __half2float(vh[gr * PART + cv + 1]);
            g_vx[gr * PART + cv]     = __float2half_rn(z0 * h0 + (1.f - z0) * ht0);
            g_vx[gr * PART + cv + 1] = __float2half_rn(z1 * h1 + (1.f - z1) * ht1);
        }
    }
}

// ---------------- projection ----------------
__global__ void __launch_bounds__(256) k_proj(const float* __restrict__ pw,
                                              const float* __restrict__ pb,
                                              float* __restrict__ out) {
    __shared__ float Ws[64 * 32];
    __shared__ float Bsh[32];
    int tid = threadIdx.x;
    for (int i = tid; i < 64 * 32; i += 256) Ws[i] = pw[i];
    if (tid < 32) Bsh[tid] = pb[tid];
    __syncthreads();
    int w = tid >> 5, lane = tid & 31;
    int g = blockIdx.x * 8 + w;
    const __half* x = g_vx + g * PART;
    float xv0 = __half2float(x[lane]);
    float xv1 = __half2float(x[32 + lane]);
    float acc = Bsh[lane];
#pragma unroll
    for (int f = 0; f < 32; f++)
        acc += __shfl_sync(0xffffffffu, xv0, f) * Ws[f * 32 + lane];
#pragma unroll
    for (int f = 0; f < 32; f++)
        acc += __shfl_sync(0xffffffffu, xv1, f) * Ws[(32 + f) * 32 + lane];
    int n = g >> 3, b = g & 7;
    out[(b * NN + n) * 32 + lane] = acc;
}

// ---------------- launch ----------------
extern "C" void kernel_launch(void* const* d_in, const int* in_sizes, int n_in,
                              void* d_out, int out_size) {
    (void)in_sizes; (void)n_in; (void)out_size;
    const float* ew = (const float*)d_in[0];
    const float* hs = (const float*)d_in[1];
    const float* go = (const float*)d_in[2];
    const float* Wz = (const float*)d_in[3];
    const float* bz = (const float*)d_in[4];
    const float* Wr = (const float*)d_in[5];
    const float* br = (const float*)d_in[6];
    const float* Wh = (const float*)d_in[7];
    const float* bh = (const float*)d_in[8];
    const float* pw = (const float*)d_in[9];
    const float* pb = (const float*)d_in[10];
    const int*   ei = (const int*)d_in[11];
    float* out = (float*)d_out;

    k_zero  <<<(NN + 255) / 256, 256>>>();
    k_degcnt<<<(EE + 255) / 256, 256>>>(ew, ei);
    k_scan  <<<2, 1024>>>();
    k_fill  <<<(EE + 255) / 256, 256>>>(ew, ei);
    k_init_x<<<(NB * HH + 255) / 256, 256>>>(go);
    k_load_h<<<(2 * NB * HH + 255) / 256, 256>>>(hs);
    k_build_wzr<<<(2 * 128 * 640 + 255) / 256, 256>>>(Wz, Wr);
    k_build_wh <<<(2 * 64 * 640 + 255) / 256, 256>>>(Wh);

    dim3 g2(NN, 2, 2), g1(NN, 1, 2);
    for (int l = 0; l < 2; l++) {
        k_prop2<<<g2, 128>>>(0, 1, l, 0, 1, 0, 2, 0, 0);   // slot1 = A_f s0; slot2 = A_r s0
        k_prop2<<<g2, 128>>>(0, 1, l, 1, 3, 2, 4, 1, 0);   // slot3/4 = 2 A(slot1/2) - s0

        k_gemm_zr<<<625, 256>>>(l, bz + l * HH, br + l * HH);

        k_prop2<<<g1, 128>>>(2, 2, l, 0, 1, 0, 2, 0, 0);
        k_prop2<<<g1, 128>>>(2, 2, l, 1, 3, 2, 4, 1, 0);

        k_gemm_h<<<625, 256>>>(l, bh + l * HH);            // -> new h in vx slot0
    }

    k_proj<<<NB / 8, 256>>>(pw, pb, out);
}